// round 2
// baseline (speedup 1.0000x reference)
#include <cuda_runtime.h>
#include <cuda_fp16.h>

#define B_ 512
#define S_ 256
#define E_ 384
#define D_ 64

// fp16 scratch (allocation-free __device__ globals), 16B-aligned for vector ops
__device__ __align__(16) __half g_Q[B_ * S_ * D_];          // [B*S][64]
__device__ __align__(16) __half g_K[B_ * S_ * D_];          // [B*S][64]
__device__ __align__(16) __half g_Vt[B_ * D_ * S_];         // [B][64][256]  (V transposed)

__device__ __forceinline__ unsigned smem_u32(const void* p) {
    return (unsigned)__cvta_generic_to_shared(p);
}

__device__ __forceinline__ void ldm_x4(unsigned* r, unsigned addr) {
    asm volatile("ldmatrix.sync.aligned.m8n8.x4.shared.b16 {%0,%1,%2,%3}, [%4];\n"
                 : "=r"(r[0]), "=r"(r[1]), "=r"(r[2]), "=r"(r[3])
                 : "r"(addr));
}

__device__ __forceinline__ void mma16816(float* c, const unsigned* a, unsigned b0, unsigned b1) {
    asm volatile("mma.sync.aligned.m16n8k16.row.col.f32.f16.f16.f32 "
                 "{%0,%1,%2,%3}, {%4,%5,%6,%7}, {%8,%9}, {%0,%1,%2,%3};\n"
                 : "+f"(c[0]), "+f"(c[1]), "+f"(c[2]), "+f"(c[3])
                 : "r"(a[0]), "r"(a[1]), "r"(a[2]), "r"(a[3]), "r"(b0), "r"(b1));
}

__device__ __forceinline__ unsigned pack_h2(float a, float b) {
    __half2 h = __floats2half2_rn(a, b);
    return *reinterpret_cast<unsigned*>(&h);
}

// ---------------------------------------------------------------------------
// Kernel 1: fused Q/K/V projection, split-fp16 (hi/lo) for ~fp32 accuracy.
// Per CTA: 128 rows x 192 cols (Q|K|V), K=384 in 6 chunks.
// 512 threads = 16 warps in a 4(m) x 4(n) grid; warp tile 32 x 48.
// ---------------------------------------------------------------------------
#define SXP 72   // X smem row stride (halves): 144B = 9*16 (ldmatrix-legal)
#define SWP 72   // Wt smem row stride (halves): 144B = 9*16 (ldmatrix-legal)

__global__ __launch_bounds__(512, 1)
void proj_kernel(const float* __restrict__ X, const float* __restrict__ Wq,
                 const float* __restrict__ Wk, const float* __restrict__ Wv) {
    extern __shared__ __half sm[];
    __half* Xh = sm;                    // [128][SXP]
    __half* Xl = Xh + 128 * SXP;
    __half* Wh = Xl + 128 * SXP;        // [192][SWP], rows = out-col (n), cols = k
    __half* Wl = Wh + 192 * SWP;

    const int tid  = threadIdx.x;
    const int lane = tid & 31;
    const int warp = tid >> 5;
    const int wm   = warp & 3;          // m offset: wm*32
    const int wn   = warp >> 2;         // n offset: wn*48
    const int m0   = blockIdx.x * 128;

    float acc[2][6][4];
#pragma unroll
    for (int i = 0; i < 2; i++)
#pragma unroll
        for (int j = 0; j < 6; j++)
#pragma unroll
            for (int k = 0; k < 4; k++) acc[i][j][k] = 0.f;

    const int ar = lane & 15;
    const int ac = (lane >> 4) << 3;
    const int br = (lane & 7) + ((lane >> 4) << 3);
    const int bc = ((lane >> 3) & 1) << 3;

    for (int kt = 0; kt < 6; kt++) {
        const int k0 = kt * 64;
        // --- load X tile 128x64 fp32 -> hi/lo halves ---
#pragma unroll
        for (int it = 0; it < 4; it++) {
            int slot = tid + it * 512;              // 0..2047 float4 slots
            int row = slot >> 4;
            int c4  = (slot & 15) << 2;
            float4 v = *reinterpret_cast<const float4*>(X + (size_t)(m0 + row) * E_ + k0 + c4);
            float vv[4] = {v.x, v.y, v.z, v.w};
            __half* ph = Xh + row * SXP + c4;
            __half* pl = Xl + row * SXP + c4;
#pragma unroll
            for (int j = 0; j < 4; j++) {
                __half h = __float2half_rn(vv[j]);
                ph[j] = h;
                pl[j] = __float2half_rn(vv[j] - __half2float(h));
            }
        }
        // --- load W chunk 64x(3x64), transposed into Wt[n][k] ---
#pragma unroll
        for (int it = 0; it < 8; it++) {
            int idx = tid + it * 512;               // 0..4095
            int k = idx >> 6;
            int n = idx & 63;
            float q  = Wq[(k0 + k) * D_ + n];
            float kk = Wk[(k0 + k) * D_ + n];
            float vv = Wv[(k0 + k) * D_ + n];
            __half hq = __float2half_rn(q);
            Wh[n * SWP + k] = hq;
            Wl[n * SWP + k] = __float2half_rn(q - __half2float(hq));
            __half hk = __float2half_rn(kk);
            Wh[(64 + n) * SWP + k] = hk;
            Wl[(64 + n) * SWP + k] = __float2half_rn(kk - __half2float(hk));
            __half hv = __float2half_rn(vv);
            Wh[(128 + n) * SWP + k] = hv;
            Wl[(128 + n) * SWP + k] = __float2half_rn(vv - __half2float(hv));
        }
        __syncthreads();

#pragma unroll
        for (int ks = 0; ks < 4; ks++) {
            const int kb = ks * 16;
            unsigned a[2][4], bh[3][4], bl[3][4];
#pragma unroll
            for (int mf = 0; mf < 2; mf++)
                ldm_x4(a[mf], smem_u32(Xh + (wm * 32 + mf * 16 + ar) * SXP + kb + ac));
#pragma unroll
            for (int bp = 0; bp < 3; bp++) {
                ldm_x4(bh[bp], smem_u32(Wh + (wn * 48 + bp * 16 + br) * SWP + kb + bc));
                ldm_x4(bl[bp], smem_u32(Wl + (wn * 48 + bp * 16 + br) * SWP + kb + bc));
            }
            // hi*hi + hi*lo
#pragma unroll
            for (int mf = 0; mf < 2; mf++)
#pragma unroll
                for (int bp = 0; bp < 3; bp++) {
                    mma16816(acc[mf][2 * bp],     a[mf], bh[bp][0], bh[bp][1]);
                    mma16816(acc[mf][2 * bp + 1], a[mf], bh[bp][2], bh[bp][3]);
                    mma16816(acc[mf][2 * bp],     a[mf], bl[bp][0], bl[bp][1]);
                    mma16816(acc[mf][2 * bp + 1], a[mf], bl[bp][2], bl[bp][3]);
                }
            // lo*hi
            unsigned al[2][4];
#pragma unroll
            for (int mf = 0; mf < 2; mf++)
                ldm_x4(al[mf], smem_u32(Xl + (wm * 32 + mf * 16 + ar) * SXP + kb + ac));
#pragma unroll
            for (int mf = 0; mf < 2; mf++)
#pragma unroll
                for (int bp = 0; bp < 3; bp++) {
                    mma16816(acc[mf][2 * bp],     al[mf], bh[bp][0], bh[bp][1]);
                    mma16816(acc[mf][2 * bp + 1], al[mf], bh[bp][2], bh[bp][3]);
                }
        }
        __syncthreads();
    }

    // --- epilogue: write Q, K (row-major fp16) and V transposed ---
    const int g  = lane >> 2;
    const int cc = (lane & 3) << 1;
#pragma unroll
    for (int mf = 0; mf < 2; mf++) {
#pragma unroll
        for (int nf = 0; nf < 6; nf++) {
            int n   = wn * 48 + nf * 8 + cc;
            int m_a = m0 + wm * 32 + mf * 16 + g;
            int m_b = m_a + 8;
            float* c = acc[mf][nf];
            if (n < 64) {
                *reinterpret_cast<__half2*>(g_Q + (size_t)m_a * D_ + n) = __floats2half2_rn(c[0], c[1]);
                *reinterpret_cast<__half2*>(g_Q + (size_t)m_b * D_ + n) = __floats2half2_rn(c[2], c[3]);
            } else if (n < 128) {
                int nn = n - 64;
                *reinterpret_cast<__half2*>(g_K + (size_t)m_a * D_ + nn) = __floats2half2_rn(c[0], c[1]);
                *reinterpret_cast<__half2*>(g_K + (size_t)m_b * D_ + nn) = __floats2half2_rn(c[2], c[3]);
            } else {
                int nn = n - 128;
                int bidx = m_a >> 8;
                int sa = m_a & 255;
                size_t base = ((size_t)bidx * D_ + nn) * S_;
                g_Vt[base + sa]          = __float2half_rn(c[0]);
                g_Vt[base + S_ + sa]     = __float2half_rn(c[1]);
                g_Vt[base + sa + 8]      = __float2half_rn(c[2]);
                g_Vt[base + S_ + sa + 8] = __float2half_rn(c[3]);
            }
        }
    }
}

// ---------------------------------------------------------------------------
// Kernel 2: causal attention. One CTA per (batch, 128-query tile).
// 8 warps x 16 query rows; online softmax over 64-key blocks.
// ---------------------------------------------------------------------------
#define SQP 72
#define SKP 72
#define SVP 264

__global__ __launch_bounds__(256, 1)
void attn_kernel(float* __restrict__ O) {
    extern __shared__ __half sm2[];
    __half* Qs = sm2;                   // [128][72]
    __half* Ks = Qs + 128 * SQP;        // [256][72]
    __half* Vs = Ks + 256 * SKP;        // [64][264] (rows = d, cols = key)

    const int tid  = threadIdx.x;
    const int lane = tid & 31;
    const int warp = tid >> 5;
    const int b    = blockIdx.y;
    const int qb   = blockIdx.x * 128;

    const __half* gq = g_Q + ((size_t)b * S_ + qb) * D_;
#pragma unroll
    for (int it = 0; it < 4; it++) {
        int idx = tid + it * 256;           // 1024 uint4
        int row = idx >> 3, c = (idx & 7) << 3;
        *reinterpret_cast<uint4*>(Qs + row * SQP + c) =
            *reinterpret_cast<const uint4*>(gq + row * D_ + c);
    }
    const __half* gk = g_K + (size_t)b * S_ * D_;
#pragma unroll
    for (int it = 0; it < 8; it++) {
        int idx = tid + it * 256;           // 2048 uint4
        int row = idx >> 3, c = (idx & 7) << 3;
        *reinterpret_cast<uint4*>(Ks + row * SKP + c) =
            *reinterpret_cast<const uint4*>(gk + row * D_ + c);
    }
    const __half* gv = g_Vt + (size_t)b * D_ * S_;
#pragma unroll
    for (int it = 0; it < 8; it++) {
        int idx = tid + it * 256;           // 2048 uint4
        int row = idx >> 5, c = (idx & 31) << 3;
        *reinterpret_cast<uint4*>(Vs + row * SVP + c) =
            *reinterpret_cast<const uint4*>(gv + row * S_ + c);
    }
    __syncthreads();

    const int ar = lane & 15;
    const int ac = (lane >> 4) << 3;
    const int br = (lane & 7) + ((lane >> 4) << 3);
    const int bc = ((lane >> 3) & 1) << 3;
    const int g  = lane >> 2;
    const int cc = (lane & 3) << 1;

    unsigned qa[4][4];
#pragma unroll
    for (int kf = 0; kf < 4; kf++)
        ldm_x4(qa[kf], smem_u32(Qs + (warp * 16 + ar) * SQP + kf * 16 + ac));

    float o[8][4];
#pragma unroll
    for (int i = 0; i < 8; i++)
#pragma unroll
        for (int j = 0; j < 4; j++) o[i][j] = 0.f;
    float mrow0 = -1e30f, mrow1 = -1e30f;
    float lrow0 = 0.f, lrow1 = 0.f;
    const int row0 = qb + warp * 16 + g;                 // thread owns row0, row0+8
    const int nkb  = ((qb + warp * 16 + 15) >> 6) + 1;   // causal early exit

    for (int kb = 0; kb < nkb; kb++) {
        float s[8][4];
#pragma unroll
        for (int i = 0; i < 8; i++)
#pragma unroll
            for (int j = 0; j < 4; j++) s[i][j] = 0.f;
        // S = Q K^T  (k over d=64)
#pragma unroll
        for (int kf = 0; kf < 4; kf++) {
#pragma unroll
            for (int bp = 0; bp < 4; bp++) {
                unsigned bk[4];
                ldm_x4(bk, smem_u32(Ks + (kb * 64 + bp * 16 + br) * SKP + kf * 16 + bc));
                mma16816(s[2 * bp],     qa[kf], bk[0], bk[1]);
                mma16816(s[2 * bp + 1], qa[kf], bk[2], bk[3]);
            }
        }
        // scale + causal mask + running max
        float mx0 = -1e30f, mx1 = -1e30f;
#pragma unroll
        for (int nf = 0; nf < 8; nf++) {
            int col = kb * 64 + nf * 8 + cc;
            s[nf][0] = (col     <= row0)     ? s[nf][0] * 0.125f : -1e30f;
            s[nf][1] = (col + 1 <= row0)     ? s[nf][1] * 0.125f : -1e30f;
            s[nf][2] = (col     <= row0 + 8) ? s[nf][2] * 0.125f : -1e30f;
            s[nf][3] = (col + 1 <= row0 + 8) ? s[nf][3] * 0.125f : -1e30f;
            mx0 = fmaxf(mx0, fmaxf(s[nf][0], s[nf][1]));
            mx1 = fmaxf(mx1, fmaxf(s[nf][2], s[nf][3]));
        }
        mx0 = fmaxf(mx0, __shfl_xor_sync(0xffffffffu, mx0, 1));
        mx0 = fmaxf(mx0, __shfl_xor_sync(0xffffffffu, mx0, 2));
        mx1 = fmaxf(mx1, __shfl_xor_sync(0xffffffffu, mx1, 1));
        mx1 = fmaxf(mx1, __shfl_xor_sync(0xffffffffu, mx1, 2));
        float mn0 = fmaxf(mrow0, mx0);
        float mn1 = fmaxf(mrow1, mx1);
        float f0 = __expf(mrow0 - mn0);
        float f1 = __expf(mrow1 - mn1);
        mrow0 = mn0; mrow1 = mn1;

        float sum0 = 0.f, sum1 = 0.f;
#pragma unroll
        for (int nf = 0; nf < 8; nf++) {
            s[nf][0] = __expf(s[nf][0] - mn0);
            s[nf][1] = __expf(s[nf][1] - mn0);
            s[nf][2] = __expf(s[nf][2] - mn1);
            s[nf][3] = __expf(s[nf][3] - mn1);
            sum0 += s[nf][0] + s[nf][1];
            sum1 += s[nf][2] + s[nf][3];
        }
        sum0 += __shfl_xor_sync(0xffffffffu, sum0, 1);
        sum0 += __shfl_xor_sync(0xffffffffu, sum0, 2);
        sum1 += __shfl_xor_sync(0xffffffffu, sum1, 1);
        sum1 += __shfl_xor_sync(0xffffffffu, sum1, 2);
        lrow0 = lrow0 * f0 + sum0;
        lrow1 = lrow1 * f1 + sum1;
#pragma unroll
        for (int nf = 0; nf < 8; nf++) {
            o[nf][0] *= f0; o[nf][1] *= f0;
            o[nf][2] *= f1; o[nf][3] *= f1;
        }
        // P (C layout) -> A fragments (register reuse, no smem round-trip)
        unsigned pa[4][4];
#pragma unroll
        for (int j = 0; j < 4; j++) {
            pa[j][0] = pack_h2(s[2 * j][0],     s[2 * j][1]);
            pa[j][1] = pack_h2(s[2 * j][2],     s[2 * j][3]);
            pa[j][2] = pack_h2(s[2 * j + 1][0], s[2 * j + 1][1]);
            pa[j][3] = pack_h2(s[2 * j + 1][2], s[2 * j + 1][3]);
        }
        // O += P @ V  (k over 64 keys of this block; B from V^T rows = d)
#pragma unroll
        for (int j = 0; j < 4; j++) {
#pragma unroll
            for (int bp = 0; bp < 4; bp++) {
                unsigned bv[4];
                ldm_x4(bv, smem_u32(Vs + (bp * 16 + br) * SVP + kb * 64 + j * 16 + bc));
                mma16816(o[2 * bp],     pa[j], bv[0], bv[1]);
                mma16816(o[2 * bp + 1], pa[j], bv[2], bv[3]);
            }
        }
    }

    const float i0 = 1.f / lrow0;
    const float i1 = 1.f / lrow1;
    float* gout = O + (size_t)b * S_ * D_;
#pragma unroll
    for (int nf = 0; nf < 8; nf++) {
        int col = nf * 8 + cc;
        float2 v0 = make_float2(o[nf][0] * i0, o[nf][1] * i0);
        float2 v1 = make_float2(o[nf][2] * i1, o[nf][3] * i1);
        *reinterpret_cast<float2*>(gout + (size_t)row0 * D_ + col)       = v0;
        *reinterpret_cast<float2*>(gout + (size_t)(row0 + 8) * D_ + col) = v1;
    }
}

// ---------------------------------------------------------------------------
extern "C" void kernel_launch(void* const* d_in, const int* in_sizes, int n_in,
                              void* d_out, int out_size) {
    (void)in_sizes; (void)n_in; (void)out_size;
    // metadata order: input_tensor, Wk, Wq, Wv
    const float* X  = (const float*)d_in[0];
    const float* Wk = (const float*)d_in[1];
    const float* Wq = (const float*)d_in[2];
    const float* Wv = (const float*)d_in[3];
    float* O = (float*)d_out;

    const int smem1 = (2 * 128 * SXP + 2 * 192 * SWP) * (int)sizeof(__half);   // 92160
    const int smem2 = (128 * SQP + 256 * SKP + 64 * SVP) * (int)sizeof(__half); // 89088
    cudaFuncSetAttribute(proj_kernel, cudaFuncAttributeMaxDynamicSharedMemorySize, smem1);
    cudaFuncSetAttribute(attn_kernel, cudaFuncAttributeMaxDynamicSharedMemorySize, smem2);

    proj_kernel<<<1024, 512, smem1>>>(X, Wq, Wk, Wv);
    attn_kernel<<<dim3(2, B_), 256, smem2>>>(O);
}

// round 5
// speedup vs baseline: 1.3528x; 1.3528x over previous
#include <cuda_runtime.h>
#include <cuda_fp16.h>

#define B_ 512
#define S_ 256
#define E_ 384
#define D_ 64

// fp16 scratch (allocation-free __device__ globals), 16B-aligned for vector ops
__device__ __align__(16) __half g_Q[B_ * S_ * D_];          // [B*S][64]
__device__ __align__(16) __half g_K[B_ * S_ * D_];          // [B*S][64]
__device__ __align__(16) __half g_Vt[B_ * D_ * S_];         // [B][64][256]  (V transposed)
// pre-split weights, n-major: [192 rows = Q|K|V outputs][384 k]
__device__ __align__(16) __half g_Wh[192 * E_];
__device__ __align__(16) __half g_Wl[192 * E_];

__device__ __forceinline__ unsigned smem_u32(const void* p) {
    return (unsigned)__cvta_generic_to_shared(p);
}

__device__ __forceinline__ void ldm_x4(unsigned* r, unsigned addr) {
    asm volatile("ldmatrix.sync.aligned.m8n8.x4.shared.b16 {%0,%1,%2,%3}, [%4];\n"
                 : "=r"(r[0]), "=r"(r[1]), "=r"(r[2]), "=r"(r[3])
                 : "r"(addr));
}

__device__ __forceinline__ void mma16816(float* c, const unsigned* a, unsigned b0, unsigned b1) {
    asm volatile("mma.sync.aligned.m16n8k16.row.col.f32.f16.f16.f32 "
                 "{%0,%1,%2,%3}, {%4,%5,%6,%7}, {%8,%9}, {%0,%1,%2,%3};\n"
                 : "+f"(c[0]), "+f"(c[1]), "+f"(c[2]), "+f"(c[3])
                 : "r"(a[0]), "r"(a[1]), "r"(a[2]), "r"(a[3]), "r"(b0), "r"(b1));
}

__device__ __forceinline__ unsigned pack_h2(float a, float b) {
    __half2 h = __floats2half2_rn(a, b);
    return *reinterpret_cast<unsigned*>(&h);
}

// ---------------------------------------------------------------------------
// Kernel 0: split W (fp32) -> hi/lo fp16, transposed to n-major [192][384].
// Runs once per launch; W is shared by all proj CTAs.
// ---------------------------------------------------------------------------
__global__ void wsplit_kernel(const float* __restrict__ Wq,
                              const float* __restrict__ Wk,
                              const float* __restrict__ Wv) {
    int idx = blockIdx.x * 256 + threadIdx.x;   // 0 .. E_*D_-1
    if (idx >= E_ * D_) return;
    int k = idx / D_;
    int n = idx % D_;
    float q = Wq[idx], kk = Wk[idx], v = Wv[idx];
    __half hq = __float2half_rn(q);
    g_Wh[n * E_ + k] = hq;
    g_Wl[n * E_ + k] = __float2half_rn(q - __half2float(hq));
    __half hk = __float2half_rn(kk);
    g_Wh[(64 + n) * E_ + k] = hk;
    g_Wl[(64 + n) * E_ + k] = __float2half_rn(kk - __half2float(hk));
    __half hv = __float2half_rn(v);
    g_Wh[(128 + n) * E_ + k] = hv;
    g_Wl[(128 + n) * E_ + k] = __float2half_rn(v - __half2float(hv));
}

// ---------------------------------------------------------------------------
// Kernel 1: fused Q/K/V projection, split-fp16 (hi/lo) for ~fp32 accuracy.
// Per CTA: 128 rows x 192 cols (Q|K|V), K=384 in 6 chunks.
// 512 threads = 16 warps in a 4(m) x 4(n) grid; warp tile 32 x 48.
// W tiles copied raw (uint4) from pre-split globals; X prefetched to regs.
// ---------------------------------------------------------------------------
#define SXP 72   // X smem row stride (halves): 144B = 9*16 (ldmatrix-legal)
#define SWP 72   // Wt smem row stride (halves): 144B = 9*16 (ldmatrix-legal)

__global__ __launch_bounds__(512, 1)
void proj_kernel(const float* __restrict__ X) {
    extern __shared__ __half sm[];
    __half* Xh = sm;                    // [128][SXP]
    __half* Xl = Xh + 128 * SXP;
    __half* Wh = Xl + 128 * SXP;        // [192][SWP], rows = out-col (n), cols = k
    __half* Wl = Wh + 192 * SWP;

    const int tid  = threadIdx.x;
    const int lane = tid & 31;
    const int warp = tid >> 5;
    const int wm   = warp & 3;          // m offset: wm*32
    const int wn   = warp >> 2;         // n offset: wn*48
    const int m0   = blockIdx.x * 128;

    float acc[2][6][4];
#pragma unroll
    for (int i = 0; i < 2; i++)
#pragma unroll
        for (int j = 0; j < 6; j++)
#pragma unroll
            for (int k = 0; k < 4; k++) acc[i][j][k] = 0.f;

    const int ar = lane & 15;
    const int ac = (lane >> 4) << 3;
    const int br = (lane & 7) + ((lane >> 4) << 3);
    const int bc = ((lane >> 3) & 1) << 3;

    // X slot geometry (fixed per thread): 4 float4 per chunk
    const int xrow0 = tid >> 4;                 // rows xrow0, +32, +64, +96
    const int xc4   = (tid & 15) << 2;
    // W copy geometry: 1536 uint4 per tile half; 512 threads x 3 iters each.
    const int wr = 0;  // (unused; geometry computed inline below)

    // prefetch chunk 0
    float4 xf[4];
#pragma unroll
    for (int it = 0; it < 4; it++)
        xf[it] = *reinterpret_cast<const float4*>(X + (size_t)(m0 + xrow0 + it * 32) * E_ + xc4);

    for (int kt = 0; kt < 6; kt++) {
        const int k0 = kt * 64;
        // --- copy W tile (raw, pre-split); power-of-2 indexing, no mod tricks ---
#pragma unroll
        for (int it = 0; it < 3; it++) {
            int idx = tid + it * 512;           // 0..1535 uint4 of the Wh tile
            int r = idx >> 3;                   // row 0..191
            int u = idx & 7;                    // uint4 within row
            *reinterpret_cast<uint4*>(Wh + r * SWP + u * 8) =
                *reinterpret_cast<const uint4*>(g_Wh + (size_t)r * E_ + k0 + u * 8);
        }
#pragma unroll
        for (int it = 0; it < 3; it++) {
            int idx = tid + it * 512;
            int r = idx >> 3;
            int u = idx & 7;
            *reinterpret_cast<uint4*>(Wl + r * SWP + u * 8) =
                *reinterpret_cast<const uint4*>(g_Wl + (size_t)r * E_ + k0 + u * 8);
        }
        // --- convert prefetched X -> hi/lo half2 stores ---
#pragma unroll
        for (int it = 0; it < 4; it++) {
            float4 v = xf[it];
            int row = xrow0 + it * 32;
            __half2 h01 = __floats2half2_rn(v.x, v.y);
            __half2 h23 = __floats2half2_rn(v.z, v.w);
            float2 f01 = __half22float2(h01);
            float2 f23 = __half22float2(h23);
            __half2 l01 = __floats2half2_rn(v.x - f01.x, v.y - f01.y);
            __half2 l23 = __floats2half2_rn(v.z - f23.x, v.w - f23.y);
            *reinterpret_cast<__half2*>(Xh + row * SXP + xc4)     = h01;
            *reinterpret_cast<__half2*>(Xh + row * SXP + xc4 + 2) = h23;
            *reinterpret_cast<__half2*>(Xl + row * SXP + xc4)     = l01;
            *reinterpret_cast<__half2*>(Xl + row * SXP + xc4 + 2) = l23;
        }
        __syncthreads();

        // --- prefetch next chunk's X (hidden under mma) ---
        if (kt < 5) {
#pragma unroll
            for (int it = 0; it < 4; it++)
                xf[it] = *reinterpret_cast<const float4*>(
                    X + (size_t)(m0 + xrow0 + it * 32) * E_ + (k0 + 64) + xc4);
        }

#pragma unroll
        for (int ks = 0; ks < 4; ks++) {
            const int kb = ks * 16;
            unsigned a[2][4], bh[3][4], bl[3][4];
#pragma unroll
            for (int mf = 0; mf < 2; mf++)
                ldm_x4(a[mf], smem_u32(Xh + (wm * 32 + mf * 16 + ar) * SXP + kb + ac));
#pragma unroll
            for (int bp = 0; bp < 3; bp++) {
                ldm_x4(bh[bp], smem_u32(Wh + (wn * 48 + bp * 16 + br) * SWP + kb + bc));
                ldm_x4(bl[bp], smem_u32(Wl + (wn * 48 + bp * 16 + br) * SWP + kb + bc));
            }
            // hi*hi + hi*lo
#pragma unroll
            for (int mf = 0; mf < 2; mf++)
#pragma unroll
                for (int bp = 0; bp < 3; bp++) {
                    mma16816(acc[mf][2 * bp],     a[mf], bh[bp][0], bh[bp][1]);
                    mma16816(acc[mf][2 * bp + 1], a[mf], bh[bp][2], bh[bp][3]);
                    mma16816(acc[mf][2 * bp],     a[mf], bl[bp][0], bl[bp][1]);
                    mma16816(acc[mf][2 * bp + 1], a[mf], bl[bp][2], bl[bp][3]);
                }
            // lo*hi
            unsigned al[2][4];
#pragma unroll
            for (int mf = 0; mf < 2; mf++)
                ldm_x4(al[mf], smem_u32(Xl + (wm * 32 + mf * 16 + ar) * SXP + kb + ac));
#pragma unroll
            for (int mf = 0; mf < 2; mf++)
#pragma unroll
                for (int bp = 0; bp < 3; bp++) {
                    mma16816(acc[mf][2 * bp],     al[mf], bh[bp][0], bh[bp][1]);
                    mma16816(acc[mf][2 * bp + 1], al[mf], bh[bp][2], bh[bp][3]);
                }
        }
        __syncthreads();
    }

    // --- epilogue: write Q, K (row-major fp16) and V transposed ---
    const int g  = lane >> 2;
    const int cc = (lane & 3) << 1;
#pragma unroll
    for (int mf = 0; mf < 2; mf++) {
#pragma unroll
        for (int nf = 0; nf < 6; nf++) {
            int n   = wn * 48 + nf * 8 + cc;
            int m_a = m0 + wm * 32 + mf * 16 + g;
            int m_b = m_a + 8;
            float* c = acc[mf][nf];
            if (n < 64) {
                *reinterpret_cast<__half2*>(g_Q + (size_t)m_a * D_ + n) = __floats2half2_rn(c[0], c[1]);
                *reinterpret_cast<__half2*>(g_Q + (size_t)m_b * D_ + n) = __floats2half2_rn(c[2], c[3]);
            } else if (n < 128) {
                int nn = n - 64;
                *reinterpret_cast<__half2*>(g_K + (size_t)m_a * D_ + nn) = __floats2half2_rn(c[0], c[1]);
                *reinterpret_cast<__half2*>(g_K + (size_t)m_b * D_ + nn) = __floats2half2_rn(c[2], c[3]);
            } else {
                int nn = n - 128;
                int bidx = m_a >> 8;
                int sa = m_a & 255;
                size_t base = ((size_t)bidx * D_ + nn) * S_;
                g_Vt[base + sa]          = __float2half_rn(c[0]);
                g_Vt[base + S_ + sa]     = __float2half_rn(c[1]);
                g_Vt[base + sa + 8]      = __float2half_rn(c[2]);
                g_Vt[base + S_ + sa + 8] = __float2half_rn(c[3]);
            }
        }
    }
}

// ---------------------------------------------------------------------------
// Kernel 2: causal attention. One CTA per (batch, 128-query tile).
// 8 warps x 16 query rows; online softmax over 64-key blocks.
// ---------------------------------------------------------------------------
#define SQP 72
#define SKP 72
#define SVP 264

__global__ __launch_bounds__(256, 1)
void attn_kernel(float* __restrict__ O) {
    extern __shared__ __half sm2[];
    __half* Qs = sm2;                   // [128][72]
    __half* Ks = Qs + 128 * SQP;        // [256][72]
    __half* Vs = Ks + 256 * SKP;        // [64][264] (rows = d, cols = key)

    const int tid  = threadIdx.x;
    const int lane = tid & 31;
    const int warp = tid >> 5;
    const int b    = blockIdx.y;
    const int qb   = blockIdx.x * 128;

    const __half* gq = g_Q + ((size_t)b * S_ + qb) * D_;
#pragma unroll
    for (int it = 0; it < 4; it++) {
        int idx = tid + it * 256;           // 1024 uint4
        int row = idx >> 3, c = (idx & 7) << 3;
        *reinterpret_cast<uint4*>(Qs + row * SQP + c) =
            *reinterpret_cast<const uint4*>(gq + row * D_ + c);
    }
    const __half* gk = g_K + (size_t)b * S_ * D_;
#pragma unroll
    for (int it = 0; it < 8; it++) {
        int idx = tid + it * 256;           // 2048 uint4
        int row = idx >> 3, c = (idx & 7) << 3;
        *reinterpret_cast<uint4*>(Ks + row * SKP + c) =
            *reinterpret_cast<const uint4*>(gk + row * D_ + c);
    }
    const __half* gv = g_Vt + (size_t)b * D_ * S_;
#pragma unroll
    for (int it = 0; it < 8; it++) {
        int idx = tid + it * 256;           // 2048 uint4
        int row = idx >> 5, c = (idx & 31) << 3;
        *reinterpret_cast<uint4*>(Vs + row * SVP + c) =
            *reinterpret_cast<const uint4*>(gv + row * S_ + c);
    }
    __syncthreads();

    const int ar = lane & 15;
    const int ac = (lane >> 4) << 3;
    const int br = (lane & 7) + ((lane >> 4) << 3);
    const int bc = ((lane >> 3) & 1) << 3;
    const int g  = lane >> 2;
    const int cc = (lane & 3) << 1;

    unsigned qa[4][4];
#pragma unroll
    for (int kf = 0; kf < 4; kf++)
        ldm_x4(qa[kf], smem_u32(Qs + (warp * 16 + ar) * SQP + kf * 16 + ac));

    float o[8][4];
#pragma unroll
    for (int i = 0; i < 8; i++)
#pragma unroll
        for (int j = 0; j < 4; j++) o[i][j] = 0.f;
    float mrow0 = -1e30f, mrow1 = -1e30f;
    float lrow0 = 0.f, lrow1 = 0.f;
    const int row0 = qb + warp * 16 + g;                 // thread owns row0, row0+8
    const int nkb  = ((qb + warp * 16 + 15) >> 6) + 1;   // causal early exit

    for (int kb = 0; kb < nkb; kb++) {
        float s[8][4];
#pragma unroll
        for (int i = 0; i < 8; i++)
#pragma unroll
            for (int j = 0; j < 4; j++) s[i][j] = 0.f;
        // S = Q K^T  (k over d=64)
#pragma unroll
        for (int kf = 0; kf < 4; kf++) {
#pragma unroll
            for (int bp = 0; bp < 4; bp++) {
                unsigned bk[4];
                ldm_x4(bk, smem_u32(Ks + (kb * 64 + bp * 16 + br) * SKP + kf * 16 + bc));
                mma16816(s[2 * bp],     qa[kf], bk[0], bk[1]);
                mma16816(s[2 * bp + 1], qa[kf], bk[2], bk[3]);
            }
        }
        // scale + causal mask + running max
        float mx0 = -1e30f, mx1 = -1e30f;
#pragma unroll
        for (int nf = 0; nf < 8; nf++) {
            int col = kb * 64 + nf * 8 + cc;
            s[nf][0] = (col     <= row0)     ? s[nf][0] * 0.125f : -1e30f;
            s[nf][1] = (col + 1 <= row0)     ? s[nf][1] * 0.125f : -1e30f;
            s[nf][2] = (col     <= row0 + 8) ? s[nf][2] * 0.125f : -1e30f;
            s[nf][3] = (col + 1 <= row0 + 8) ? s[nf][3] * 0.125f : -1e30f;
            mx0 = fmaxf(mx0, fmaxf(s[nf][0], s[nf][1]));
            mx1 = fmaxf(mx1, fmaxf(s[nf][2], s[nf][3]));
        }
        mx0 = fmaxf(mx0, __shfl_xor_sync(0xffffffffu, mx0, 1));
        mx0 = fmaxf(mx0, __shfl_xor_sync(0xffffffffu, mx0, 2));
        mx1 = fmaxf(mx1, __shfl_xor_sync(0xffffffffu, mx1, 1));
        mx1 = fmaxf(mx1, __shfl_xor_sync(0xffffffffu, mx1, 2));
        float mn0 = fmaxf(mrow0, mx0);
        float mn1 = fmaxf(mrow1, mx1);
        float f0 = __expf(mrow0 - mn0);
        float f1 = __expf(mrow1 - mn1);
        mrow0 = mn0; mrow1 = mn1;

        float sum0 = 0.f, sum1 = 0.f;
#pragma unroll
        for (int nf = 0; nf < 8; nf++) {
            s[nf][0] = __expf(s[nf][0] - mn0);
            s[nf][1] = __expf(s[nf][1] - mn0);
            s[nf][2] = __expf(s[nf][2] - mn1);
            s[nf][3] = __expf(s[nf][3] - mn1);
            sum0 += s[nf][0] + s[nf][1];
            sum1 += s[nf][2] + s[nf][3];
        }
        sum0 += __shfl_xor_sync(0xffffffffu, sum0, 1);
        sum0 += __shfl_xor_sync(0xffffffffu, sum0, 2);
        sum1 += __shfl_xor_sync(0xffffffffu, sum1, 1);
        sum1 += __shfl_xor_sync(0xffffffffu, sum1, 2);
        lrow0 = lrow0 * f0 + sum0;
        lrow1 = lrow1 * f1 + sum1;
#pragma unroll
        for (int nf = 0; nf < 8; nf++) {
            o[nf][0] *= f0; o[nf][1] *= f0;
            o[nf][2] *= f1; o[nf][3] *= f1;
        }
        // P (C layout) -> A fragments (register reuse, no smem round-trip)
        unsigned pa[4][4];
#pragma unroll
        for (int j = 0; j < 4; j++) {
            pa[j][0] = pack_h2(s[2 * j][0],     s[2 * j][1]);
            pa[j][1] = pack_h2(s[2 * j][2],     s[2 * j][3]);
            pa[j][2] = pack_h2(s[2 * j + 1][0], s[2 * j + 1][1]);
            pa[j][3] = pack_h2(s[2 * j + 1][2], s[2 * j + 1][3]);
        }
        // O += P @ V  (k over 64 keys of this block; B from V^T rows = d)
#pragma unroll
        for (int j = 0; j < 4; j++) {
#pragma unroll
            for (int bp = 0; bp < 4; bp++) {
                unsigned bv[4];
                ldm_x4(bv, smem_u32(Vs + (bp * 16 + br) * SVP + kb * 64 + j * 16 + bc));
                mma16816(o[2 * bp],     pa[j], bv[0], bv[1]);
                mma16816(o[2 * bp + 1], pa[j], bv[2], bv[3]);
            }
        }
    }

    const float i0 = 1.f / lrow0;
    const float i1 = 1.f / lrow1;
    float* gout = O + (size_t)b * S_ * D_;
#pragma unroll
    for (int nf = 0; nf < 8; nf++) {
        int col = nf * 8 + cc;
        float2 v0 = make_float2(o[nf][0] * i0, o[nf][1] * i0);
        float2 v1 = make_float2(o[nf][2] * i1, o[nf][3] * i1);
        *reinterpret_cast<float2*>(gout + (size_t)row0 * D_ + col)       = v0;
        *reinterpret_cast<float2*>(gout + (size_t)(row0 + 8) * D_ + col) = v1;
    }
}

// ---------------------------------------------------------------------------
extern "C" void kernel_launch(void* const* d_in, const int* in_sizes, int n_in,
                              void* d_out, int out_size) {
    (void)in_sizes; (void)n_in; (void)out_size;
    // metadata order: input_tensor, Wk, Wq, Wv
    const float* X  = (const float*)d_in[0];
    const float* Wk = (const float*)d_in[1];
    const float* Wq = (const float*)d_in[2];
    const float* Wv = (const float*)d_in[3];
    float* O = (float*)d_out;

    const int smem1 = (2 * 128 * SXP + 2 * 192 * SWP) * (int)sizeof(__half);   // 92160
    const int smem2 = (128 * SQP + 256 * SKP + 64 * SVP) * (int)sizeof(__half); // 89088
    cudaFuncSetAttribute(proj_kernel, cudaFuncAttributeMaxDynamicSharedMemorySize, smem1);
    cudaFuncSetAttribute(attn_kernel, cudaFuncAttributeMaxDynamicSharedMemorySize, smem2);

    wsplit_kernel<<<(E_ * D_ + 255) / 256, 256>>>(Wq, Wk, Wv);
    proj_kernel<<<1024, 512, smem1>>>(X);
    attn_kernel<<<dim3(2, B_), 256, smem2>>>(O);
}

// round 6
// speedup vs baseline: 1.3762x; 1.0173x over previous
#include <cuda_runtime.h>
#include <cuda_fp16.h>

#define B_ 512
#define S_ 256
#define E_ 384
#define D_ 64

// fp16 scratch (allocation-free __device__ globals), 16B-aligned for vector ops
__device__ __align__(16) __half g_Q[B_ * S_ * D_];          // [B*S][64]
__device__ __align__(16) __half g_K[B_ * S_ * D_];          // [B*S][64]
__device__ __align__(16) __half g_Vt[B_ * D_ * S_];         // [B][64][256]  (V transposed)
// pre-split weights, n-major: [192 rows = Q|K|V outputs][384 k]
__device__ __align__(16) __half g_Wh[192 * E_];
__device__ __align__(16) __half g_Wl[192 * E_];

__device__ __forceinline__ unsigned smem_u32(const void* p) {
    return (unsigned)__cvta_generic_to_shared(p);
}

__device__ __forceinline__ void ldm_x4(unsigned* r, unsigned addr) {
    asm volatile("ldmatrix.sync.aligned.m8n8.x4.shared.b16 {%0,%1,%2,%3}, [%4];\n"
                 : "=r"(r[0]), "=r"(r[1]), "=r"(r[2]), "=r"(r[3])
                 : "r"(addr));
}

__device__ __forceinline__ void mma16816(float* c, const unsigned* a, unsigned b0, unsigned b1) {
    asm volatile("mma.sync.aligned.m16n8k16.row.col.f32.f16.f16.f32 "
                 "{%0,%1,%2,%3}, {%4,%5,%6,%7}, {%8,%9}, {%0,%1,%2,%3};\n"
                 : "+f"(c[0]), "+f"(c[1]), "+f"(c[2]), "+f"(c[3])
                 : "r"(a[0]), "r"(a[1]), "r"(a[2]), "r"(a[3]), "r"(b0), "r"(b1));
}

__device__ __forceinline__ unsigned pack_h2(float a, float b) {
    __half2 h = __floats2half2_rn(a, b);
    return *reinterpret_cast<unsigned*>(&h);
}

__device__ __forceinline__ void cp_async16(void* dst_smem, const void* src) {
    asm volatile("cp.async.cg.shared.global [%0], [%1], 16;\n"
                 :: "r"(smem_u32(dst_smem)), "l"(src));
}
#define CP_COMMIT() asm volatile("cp.async.commit_group;\n" ::: "memory")
#define CP_WAIT0()  asm volatile("cp.async.wait_group 0;\n" ::: "memory")

// ---------------------------------------------------------------------------
// Kernel 0: split W (fp32) -> hi/lo fp16, transposed to n-major [192][384].
// ---------------------------------------------------------------------------
__global__ void wsplit_kernel(const float* __restrict__ Wq,
                              const float* __restrict__ Wk,
                              const float* __restrict__ Wv) {
    int idx = blockIdx.x * 256 + threadIdx.x;   // 0 .. E_*D_-1
    if (idx >= E_ * D_) return;
    int k = idx / D_;
    int n = idx % D_;
    float q = Wq[idx], kk = Wk[idx], v = Wv[idx];
    __half hq = __float2half_rn(q);
    g_Wh[n * E_ + k] = hq;
    g_Wl[n * E_ + k] = __float2half_rn(q - __half2float(hq));
    __half hk = __float2half_rn(kk);
    g_Wh[(64 + n) * E_ + k] = hk;
    g_Wl[(64 + n) * E_ + k] = __float2half_rn(kk - __half2float(hk));
    __half hv = __float2half_rn(v);
    g_Wh[(128 + n) * E_ + k] = hv;
    g_Wl[(128 + n) * E_ + k] = __float2half_rn(v - __half2float(hv));
}

// ---------------------------------------------------------------------------
// Kernel 1: fused Q/K/V projection, split-fp16, double-buffered cp.async.
// Per CTA: 128 rows x 192 cols (Q|K|V), K=384 in 6 chunks.
// 512 threads = 16 warps in a 4(m) x 4(n) grid; warp tile 32 x 48.
// ---------------------------------------------------------------------------
#define SXP 72   // X smem row stride (halves): 144B = 9*16 (ldmatrix-legal)
#define SWP 72   // Wt smem row stride (halves)
#define XH_SZ (128 * SXP)   // 9216 halves per X buffer
#define WH_SZ (192 * SWP)   // 13824 halves per W buffer

__global__ __launch_bounds__(512, 1)
void proj_kernel(const float* __restrict__ X) {
    extern __shared__ __half sm[];
    // layout: Xh[2] | Xl[2] | Wh[2] | Wl[2]
    __half* XhB = sm;
    __half* XlB = XhB + 2 * XH_SZ;
    __half* WhB = XlB + 2 * XH_SZ;
    __half* WlB = WhB + 2 * WH_SZ;

    const int tid  = threadIdx.x;
    const int lane = tid & 31;
    const int warp = tid >> 5;
    const int wm   = warp & 3;          // m offset: wm*32
    const int wn   = warp >> 2;         // n offset: wn*48
    const int m0   = blockIdx.x * 128;

    float acc[2][6][4];
#pragma unroll
    for (int i = 0; i < 2; i++)
#pragma unroll
        for (int j = 0; j < 6; j++)
#pragma unroll
            for (int k = 0; k < 4; k++) acc[i][j][k] = 0.f;

    const int ar = lane & 15;
    const int ac = (lane >> 4) << 3;
    const int br = (lane & 7) + ((lane >> 4) << 3);
    const int bc = ((lane >> 3) & 1) << 3;

    // X slot geometry (fixed per thread): 4 float4 per chunk
    const int xrow0 = tid >> 4;                 // rows xrow0, +32, +64, +96
    const int xc4   = (tid & 15) << 2;
    // W copy geometry: 1536 uint4 per tile half; 512 threads x 3 iters each.
    const int wr = tid >> 3;                    // base row (of 64-row groups x3)
    const int wu = tid & 7;

    // ---- prologue: W chunk 0 via cp.async, X chunk 0 via regs ----
#pragma unroll
    for (int it = 0; it < 3; it++) {
        int r = wr + it * 64;
        cp_async16(WhB + r * SWP + wu * 8, g_Wh + (size_t)r * E_ + wu * 8);
    }
#pragma unroll
    for (int it = 0; it < 3; it++) {
        int r = wr + it * 64;
        cp_async16(WlB + r * SWP + wu * 8, g_Wl + (size_t)r * E_ + wu * 8);
    }
    CP_COMMIT();

    float4 xf[4];
#pragma unroll
    for (int it = 0; it < 4; it++)
        xf[it] = *reinterpret_cast<const float4*>(X + (size_t)(m0 + xrow0 + it * 32) * E_ + xc4);
#pragma unroll
    for (int it = 0; it < 4; it++) {
        float4 v = xf[it];
        int row = xrow0 + it * 32;
        __half2 h01 = __floats2half2_rn(v.x, v.y);
        __half2 h23 = __floats2half2_rn(v.z, v.w);
        float2 f01 = __half22float2(h01);
        float2 f23 = __half22float2(h23);
        *reinterpret_cast<__half2*>(XhB + row * SXP + xc4)     = h01;
        *reinterpret_cast<__half2*>(XhB + row * SXP + xc4 + 2) = h23;
        *reinterpret_cast<__half2*>(XlB + row * SXP + xc4)     = __floats2half2_rn(v.x - f01.x, v.y - f01.y);
        *reinterpret_cast<__half2*>(XlB + row * SXP + xc4 + 2) = __floats2half2_rn(v.z - f23.x, v.w - f23.y);
    }
    CP_WAIT0();
    __syncthreads();

    for (int kt = 0; kt < 6; kt++) {
        const int buf  = kt & 1;
        const int nbuf = buf ^ 1;
        __half* Xh = XhB + buf * XH_SZ;
        __half* Xl = XlB + buf * XH_SZ;
        __half* Wh = WhB + buf * WH_SZ;
        __half* Wl = WlB + buf * WH_SZ;

        // ---- issue next chunk's W cp.async + X LDG (hidden under mma) ----
        if (kt < 5) {
            const int k1 = (kt + 1) * 64;
            __half* WhN = WhB + nbuf * WH_SZ;
            __half* WlN = WlB + nbuf * WH_SZ;
#pragma unroll
            for (int it = 0; it < 3; it++) {
                int r = wr + it * 64;
                cp_async16(WhN + r * SWP + wu * 8, g_Wh + (size_t)r * E_ + k1 + wu * 8);
            }
#pragma unroll
            for (int it = 0; it < 3; it++) {
                int r = wr + it * 64;
                cp_async16(WlN + r * SWP + wu * 8, g_Wl + (size_t)r * E_ + k1 + wu * 8);
            }
            CP_COMMIT();
#pragma unroll
            for (int it = 0; it < 4; it++)
                xf[it] = *reinterpret_cast<const float4*>(
                    X + (size_t)(m0 + xrow0 + it * 32) * E_ + k1 + xc4);
        }

        // ---- mma over current buffers; 3 passes for RAW distance ----
#pragma unroll
        for (int ks = 0; ks < 4; ks++) {
            const int kb = ks * 16;
            unsigned a[2][4], al[2][4], bh[3][4], bl[3][4];
#pragma unroll
            for (int mf = 0; mf < 2; mf++)
                ldm_x4(a[mf], smem_u32(Xh + (wm * 32 + mf * 16 + ar) * SXP + kb + ac));
#pragma unroll
            for (int bp = 0; bp < 3; bp++)
                ldm_x4(bh[bp], smem_u32(Wh + (wn * 48 + bp * 16 + br) * SWP + kb + bc));
            // pass 1: hi*hi
#pragma unroll
            for (int mf = 0; mf < 2; mf++)
#pragma unroll
                for (int bp = 0; bp < 3; bp++) {
                    mma16816(acc[mf][2 * bp],     a[mf], bh[bp][0], bh[bp][1]);
                    mma16816(acc[mf][2 * bp + 1], a[mf], bh[bp][2], bh[bp][3]);
                }
#pragma unroll
            for (int bp = 0; bp < 3; bp++)
                ldm_x4(bl[bp], smem_u32(Wl + (wn * 48 + bp * 16 + br) * SWP + kb + bc));
            // pass 2: hi*lo
#pragma unroll
            for (int mf = 0; mf < 2; mf++)
#pragma unroll
                for (int bp = 0; bp < 3; bp++) {
                    mma16816(acc[mf][2 * bp],     a[mf], bl[bp][0], bl[bp][1]);
                    mma16816(acc[mf][2 * bp + 1], a[mf], bl[bp][2], bl[bp][3]);
                }
#pragma unroll
            for (int mf = 0; mf < 2; mf++)
                ldm_x4(al[mf], smem_u32(Xl + (wm * 32 + mf * 16 + ar) * SXP + kb + ac));
            // pass 3: lo*hi
#pragma unroll
            for (int mf = 0; mf < 2; mf++)
#pragma unroll
                for (int bp = 0; bp < 3; bp++) {
                    mma16816(acc[mf][2 * bp],     al[mf], bh[bp][0], bh[bp][1]);
                    mma16816(acc[mf][2 * bp + 1], al[mf], bh[bp][2], bh[bp][3]);
                }
        }

        // ---- convert next X into alternate buffer (after mma issue) ----
        if (kt < 5) {
            __half* XhN = XhB + nbuf * XH_SZ;
            __half* XlN = XlB + nbuf * XH_SZ;
#pragma unroll
            for (int it = 0; it < 4; it++) {
                float4 v = xf[it];
                int row = xrow0 + it * 32;
                __half2 h01 = __floats2half2_rn(v.x, v.y);
                __half2 h23 = __floats2half2_rn(v.z, v.w);
                float2 f01 = __half22float2(h01);
                float2 f23 = __half22float2(h23);
                *reinterpret_cast<__half2*>(XhN + row * SXP + xc4)     = h01;
                *reinterpret_cast<__half2*>(XhN + row * SXP + xc4 + 2) = h23;
                *reinterpret_cast<__half2*>(XlN + row * SXP + xc4)     = __floats2half2_rn(v.x - f01.x, v.y - f01.y);
                *reinterpret_cast<__half2*>(XlN + row * SXP + xc4 + 2) = __floats2half2_rn(v.z - f23.x, v.w - f23.y);
            }
        }
        CP_WAIT0();
        __syncthreads();
    }

    // --- epilogue: write Q, K (row-major fp16) and V transposed ---
    const int g  = lane >> 2;
    const int cc = (lane & 3) << 1;
#pragma unroll
    for (int mf = 0; mf < 2; mf++) {
#pragma unroll
        for (int nf = 0; nf < 6; nf++) {
            int n   = wn * 48 + nf * 8 + cc;
            int m_a = m0 + wm * 32 + mf * 16 + g;
            int m_b = m_a + 8;
            float* c = acc[mf][nf];
            if (n < 64) {
                *reinterpret_cast<__half2*>(g_Q + (size_t)m_a * D_ + n) = __floats2half2_rn(c[0], c[1]);
                *reinterpret_cast<__half2*>(g_Q + (size_t)m_b * D_ + n) = __floats2half2_rn(c[2], c[3]);
            } else if (n < 128) {
                int nn = n - 64;
                *reinterpret_cast<__half2*>(g_K + (size_t)m_a * D_ + nn) = __floats2half2_rn(c[0], c[1]);
                *reinterpret_cast<__half2*>(g_K + (size_t)m_b * D_ + nn) = __floats2half2_rn(c[2], c[3]);
            } else {
                int nn = n - 128;
                int bidx = m_a >> 8;
                int sa = m_a & 255;
                size_t base = ((size_t)bidx * D_ + nn) * S_;
                g_Vt[base + sa]          = __float2half_rn(c[0]);
                g_Vt[base + S_ + sa]     = __float2half_rn(c[1]);
                g_Vt[base + sa + 8]      = __float2half_rn(c[2]);
                g_Vt[base + S_ + sa + 8] = __float2half_rn(c[3]);
            }
        }
    }
}

// ---------------------------------------------------------------------------
// Kernel 2: causal attention. One CTA per (batch, 128-query tile).
// 8 warps x 16 query rows; online softmax over 64-key blocks. 2 CTAs/SM.
// ---------------------------------------------------------------------------
#define SQP 72
#define SKP 72
#define SVP 264

__global__ __launch_bounds__(256, 2)
void attn_kernel(float* __restrict__ O) {
    extern __shared__ __half sm2[];
    __half* Qs = sm2;                   // [128][72]
    __half* Ks = Qs + 128 * SQP;        // [256][72]
    __half* Vs = Ks + 256 * SKP;        // [64][264] (rows = d, cols = key)

    const int tid  = threadIdx.x;
    const int lane = tid & 31;
    const int warp = tid >> 5;
    const int b    = blockIdx.y;
    const int qb   = blockIdx.x * 128;

    const __half* gq = g_Q + ((size_t)b * S_ + qb) * D_;
#pragma unroll
    for (int it = 0; it < 4; it++) {
        int idx = tid + it * 256;           // 1024 uint4
        int row = idx >> 3, c = (idx & 7) << 3;
        *reinterpret_cast<uint4*>(Qs + row * SQP + c) =
            *reinterpret_cast<const uint4*>(gq + row * D_ + c);
    }
    const __half* gk = g_K + (size_t)b * S_ * D_;
#pragma unroll
    for (int it = 0; it < 8; it++) {
        int idx = tid + it * 256;           // 2048 uint4
        int row = idx >> 3, c = (idx & 7) << 3;
        *reinterpret_cast<uint4*>(Ks + row * SKP + c) =
            *reinterpret_cast<const uint4*>(gk + row * D_ + c);
    }
    const __half* gv = g_Vt + (size_t)b * D_ * S_;
#pragma unroll
    for (int it = 0; it < 8; it++) {
        int idx = tid + it * 256;           // 2048 uint4
        int row = idx >> 5, c = (idx & 31) << 3;
        *reinterpret_cast<uint4*>(Vs + row * SVP + c) =
            *reinterpret_cast<const uint4*>(gv + row * S_ + c);
    }
    __syncthreads();

    const int ar = lane & 15;
    const int ac = (lane >> 4) << 3;
    const int br = (lane & 7) + ((lane >> 4) << 3);
    const int bc = ((lane >> 3) & 1) << 3;
    const int g  = lane >> 2;
    const int cc = (lane & 3) << 1;

    unsigned qa[4][4];
#pragma unroll
    for (int kf = 0; kf < 4; kf++)
        ldm_x4(qa[kf], smem_u32(Qs + (warp * 16 + ar) * SQP + kf * 16 + ac));

    float o[8][4];
#pragma unroll
    for (int i = 0; i < 8; i++)
#pragma unroll
        for (int j = 0; j < 4; j++) o[i][j] = 0.f;
    float mrow0 = -1e30f, mrow1 = -1e30f;
    float lrow0 = 0.f, lrow1 = 0.f;
    const int row0 = qb + warp * 16 + g;                 // thread owns row0, row0+8
    const int nkb  = ((qb + warp * 16 + 15) >> 6) + 1;   // causal early exit

    for (int kb = 0; kb < nkb; kb++) {
        float s[8][4];
#pragma unroll
        for (int i = 0; i < 8; i++)
#pragma unroll
            for (int j = 0; j < 4; j++) s[i][j] = 0.f;
        // S = Q K^T  (k over d=64)
#pragma unroll
        for (int kf = 0; kf < 4; kf++) {
#pragma unroll
            for (int bp = 0; bp < 4; bp++) {
                unsigned bk[4];
                ldm_x4(bk, smem_u32(Ks + (kb * 64 + bp * 16 + br) * SKP + kf * 16 + bc));
                mma16816(s[2 * bp],     qa[kf], bk[0], bk[1]);
                mma16816(s[2 * bp + 1], qa[kf], bk[2], bk[3]);
            }
        }
        // scale + causal mask + running max
        float mx0 = -1e30f, mx1 = -1e30f;
#pragma unroll
        for (int nf = 0; nf < 8; nf++) {
            int col = kb * 64 + nf * 8 + cc;
            s[nf][0] = (col     <= row0)     ? s[nf][0] * 0.125f : -1e30f;
            s[nf][1] = (col + 1 <= row0)     ? s[nf][1] * 0.125f : -1e30f;
            s[nf][2] = (col     <= row0 + 8) ? s[nf][2] * 0.125f : -1e30f;
            s[nf][3] = (col + 1 <= row0 + 8) ? s[nf][3] * 0.125f : -1e30f;
            mx0 = fmaxf(mx0, fmaxf(s[nf][0], s[nf][1]));
            mx1 = fmaxf(mx1, fmaxf(s[nf][2], s[nf][3]));
        }
        mx0 = fmaxf(mx0, __shfl_xor_sync(0xffffffffu, mx0, 1));
        mx0 = fmaxf(mx0, __shfl_xor_sync(0xffffffffu, mx0, 2));
        mx1 = fmaxf(mx1, __shfl_xor_sync(0xffffffffu, mx1, 1));
        mx1 = fmaxf(mx1, __shfl_xor_sync(0xffffffffu, mx1, 2));
        float mn0 = fmaxf(mrow0, mx0);
        float mn1 = fmaxf(mrow1, mx1);
        float f0 = __expf(mrow0 - mn0);
        float f1 = __expf(mrow1 - mn1);
        mrow0 = mn0; mrow1 = mn1;

        float sum0 = 0.f, sum1 = 0.f;
#pragma unroll
        for (int nf = 0; nf < 8; nf++) {
            s[nf][0] = __expf(s[nf][0] - mn0);
            s[nf][1] = __expf(s[nf][1] - mn0);
            s[nf][2] = __expf(s[nf][2] - mn1);
            s[nf][3] = __expf(s[nf][3] - mn1);
            sum0 += s[nf][0] + s[nf][1];
            sum1 += s[nf][2] + s[nf][3];
        }
        sum0 += __shfl_xor_sync(0xffffffffu, sum0, 1);
        sum0 += __shfl_xor_sync(0xffffffffu, sum0, 2);
        sum1 += __shfl_xor_sync(0xffffffffu, sum1, 1);
        sum1 += __shfl_xor_sync(0xffffffffu, sum1, 2);
        lrow0 = lrow0 * f0 + sum0;
        lrow1 = lrow1 * f1 + sum1;
#pragma unroll
        for (int nf = 0; nf < 8; nf++) {
            o[nf][0] *= f0; o[nf][1] *= f0;
            o[nf][2] *= f1; o[nf][3] *= f1;
        }
        // P (C layout) -> A fragments (register reuse, no smem round-trip)
        unsigned pa[4][4];
#pragma unroll
        for (int j = 0; j < 4; j++) {
            pa[j][0] = pack_h2(s[2 * j][0],     s[2 * j][1]);
            pa[j][1] = pack_h2(s[2 * j][2],     s[2 * j][3]);
            pa[j][2] = pack_h2(s[2 * j + 1][0], s[2 * j + 1][1]);
            pa[j][3] = pack_h2(s[2 * j + 1][2], s[2 * j + 1][3]);
        }
        // O += P @ V  (k over 64 keys of this block; B from V^T rows = d)
#pragma unroll
        for (int j = 0; j < 4; j++) {
#pragma unroll
            for (int bp = 0; bp < 4; bp++) {
                unsigned bv[4];
                ldm_x4(bv, smem_u32(Vs + (bp * 16 + br) * SVP + kb * 64 + j * 16 + bc));
                mma16816(o[2 * bp],     pa[j], bv[0], bv[1]);
                mma16816(o[2 * bp + 1], pa[j], bv[2], bv[3]);
            }
        }
    }

    const float i0 = 1.f / lrow0;
    const float i1 = 1.f / lrow1;
    float* gout = O + (size_t)b * S_ * D_;
#pragma unroll
    for (int nf = 0; nf < 8; nf++) {
        int col = nf * 8 + cc;
        float2 v0 = make_float2(o[nf][0] * i0, o[nf][1] * i0);
        float2 v1 = make_float2(o[nf][2] * i1, o[nf][3] * i1);
        *reinterpret_cast<float2*>(gout + (size_t)row0 * D_ + col)       = v0;
        *reinterpret_cast<float2*>(gout + (size_t)(row0 + 8) * D_ + col) = v1;
    }
}

// ---------------------------------------------------------------------------
extern "C" void kernel_launch(void* const* d_in, const int* in_sizes, int n_in,
                              void* d_out, int out_size) {
    (void)in_sizes; (void)n_in; (void)out_size;
    // metadata order: input_tensor, Wk, Wq, Wv
    const float* X  = (const float*)d_in[0];
    const float* Wk = (const float*)d_in[1];
    const float* Wq = (const float*)d_in[2];
    const float* Wv = (const float*)d_in[3];
    float* O = (float*)d_out;

    const int smem1 = (4 * XH_SZ + 4 * WH_SZ) * (int)sizeof(__half);           // 184320
    const int smem2 = (128 * SQP + 256 * SKP + 64 * SVP) * (int)sizeof(__half); // 89088
    cudaFuncSetAttribute(proj_kernel, cudaFuncAttributeMaxDynamicSharedMemorySize, smem1);
    cudaFuncSetAttribute(attn_kernel, cudaFuncAttributeMaxDynamicSharedMemorySize, smem2);

    wsplit_kernel<<<(E_ * D_ + 255) / 256, 256>>>(Wq, Wk, Wv);
    proj_kernel<<<1024, 512, smem1>>>(X);
    attn_kernel<<<dim3(2, B_), 256, smem2>>>(O);
}

// round 7
// speedup vs baseline: 1.3787x; 1.0018x over previous
#include <cuda_runtime.h>
#include <cuda_fp16.h>

#define B_ 512
#define S_ 256
#define E_ 384
#define D_ 64

// fp16 scratch (allocation-free __device__ globals), 16B-aligned for vector ops
__device__ __align__(16) __half g_Q[B_ * S_ * D_];          // [B*S][64]
__device__ __align__(16) __half g_K[B_ * S_ * D_];          // [B*S][64]
__device__ __align__(16) __half g_Vt[B_ * D_ * S_];         // [B][64][256]  (V transposed)
// pre-split weights, n-major: [192 rows = Q|K|V outputs][384 k]
__device__ __align__(16) __half g_Wh[192 * E_];
__device__ __align__(16) __half g_Wl[192 * E_];

__device__ __forceinline__ unsigned smem_u32(const void* p) {
    return (unsigned)__cvta_generic_to_shared(p);
}

__device__ __forceinline__ void ldm_x4(unsigned* r, unsigned addr) {
    asm volatile("ldmatrix.sync.aligned.m8n8.x4.shared.b16 {%0,%1,%2,%3}, [%4];\n"
                 : "=r"(r[0]), "=r"(r[1]), "=r"(r[2]), "=r"(r[3])
                 : "r"(addr));
}

__device__ __forceinline__ void mma16816(float* c, const unsigned* a, unsigned b0, unsigned b1) {
    asm volatile("mma.sync.aligned.m16n8k16.row.col.f32.f16.f16.f32 "
                 "{%0,%1,%2,%3}, {%4,%5,%6,%7}, {%8,%9}, {%0,%1,%2,%3};\n"
                 : "+f"(c[0]), "+f"(c[1]), "+f"(c[2]), "+f"(c[3])
                 : "r"(a[0]), "r"(a[1]), "r"(a[2]), "r"(a[3]), "r"(b0), "r"(b1));
}

__device__ __forceinline__ unsigned pack_h2(float a, float b) {
    __half2 h = __floats2half2_rn(a, b);
    return *reinterpret_cast<unsigned*>(&h);
}

__device__ __forceinline__ void cp_async16(void* dst_smem, const void* src) {
    asm volatile("cp.async.cg.shared.global [%0], [%1], 16;\n"
                 :: "r"(smem_u32(dst_smem)), "l"(src));
}
#define CP_COMMIT() asm volatile("cp.async.commit_group;\n" ::: "memory")
#define CP_WAIT0()  asm volatile("cp.async.wait_group 0;\n" ::: "memory")

// ---------------------------------------------------------------------------
// Kernel 0: split W (fp32) -> hi/lo fp16, transposed to n-major [192][384].
// ---------------------------------------------------------------------------
__global__ void wsplit_kernel(const float* __restrict__ Wq,
                              const float* __restrict__ Wk,
                              const float* __restrict__ Wv) {
    int idx = blockIdx.x * 256 + threadIdx.x;   // 0 .. E_*D_-1
    if (idx >= E_ * D_) return;
    int k = idx / D_;
    int n = idx % D_;
    float q = Wq[idx], kk = Wk[idx], v = Wv[idx];
    __half hq = __float2half_rn(q);
    g_Wh[n * E_ + k] = hq;
    g_Wl[n * E_ + k] = __float2half_rn(q - __half2float(hq));
    __half hk = __float2half_rn(kk);
    g_Wh[(64 + n) * E_ + k] = hk;
    g_Wl[(64 + n) * E_ + k] = __float2half_rn(kk - __half2float(hk));
    __half hv = __float2half_rn(v);
    g_Wh[(128 + n) * E_ + k] = hv;
    g_Wl[(128 + n) * E_ + k] = __float2half_rn(v - __half2float(hv));
}

// ---------------------------------------------------------------------------
// Kernel 1: fused Q/K/V projection, split-fp16, double-buffered cp.async.
// Per CTA: 128 rows x 192 cols (Q|K|V), K=384 in 6 chunks.
// 512 threads = 16 warps in a 4(m) x 4(n) grid; warp tile 32 x 48.
// ---------------------------------------------------------------------------
#define SXP 72   // X smem row stride (halves): 144B = 9*16 (ldmatrix-legal)
#define SWP 72   // Wt smem row stride (halves)
#define XH_SZ (128 * SXP)   // 9216 halves per X buffer
#define WH_SZ (192 * SWP)   // 13824 halves per W buffer

__global__ __launch_bounds__(512, 1)
void proj_kernel(const float* __restrict__ X) {
    extern __shared__ __half sm[];
    // layout: Xh[2] | Xl[2] | Wh[2] | Wl[2]
    __half* XhB = sm;
    __half* XlB = XhB + 2 * XH_SZ;
    __half* WhB = XlB + 2 * XH_SZ;
    __half* WlB = WhB + 2 * WH_SZ;

    const int tid  = threadIdx.x;
    const int lane = tid & 31;
    const int warp = tid >> 5;
    const int wm   = warp & 3;          // m offset: wm*32
    const int wn   = warp >> 2;         // n offset: wn*48
    const int m0   = blockIdx.x * 128;

    float acc[2][6][4];
#pragma unroll
    for (int i = 0; i < 2; i++)
#pragma unroll
        for (int j = 0; j < 6; j++)
#pragma unroll
            for (int k = 0; k < 4; k++) acc[i][j][k] = 0.f;

    const int ar = lane & 15;
    const int ac = (lane >> 4) << 3;
    const int br = (lane & 7) + ((lane >> 4) << 3);
    const int bc = ((lane >> 3) & 1) << 3;

    // X slot geometry (fixed per thread): 4 float4 per chunk
    const int xrow0 = tid >> 4;                 // rows xrow0, +32, +64, +96
    const int xc4   = (tid & 15) << 2;
    // W copy geometry: 1536 uint4 per tile half; 512 threads x 3 iters each.
    const int wr = tid >> 3;                    // base row (of 64-row groups x3)
    const int wu = tid & 7;

    // ---- prologue: W chunk 0 via cp.async, X chunk 0 via regs ----
#pragma unroll
    for (int it = 0; it < 3; it++) {
        int r = wr + it * 64;
        cp_async16(WhB + r * SWP + wu * 8, g_Wh + (size_t)r * E_ + wu * 8);
    }
#pragma unroll
    for (int it = 0; it < 3; it++) {
        int r = wr + it * 64;
        cp_async16(WlB + r * SWP + wu * 8, g_Wl + (size_t)r * E_ + wu * 8);
    }
    CP_COMMIT();

    float4 xf[4];
#pragma unroll
    for (int it = 0; it < 4; it++)
        xf[it] = *reinterpret_cast<const float4*>(X + (size_t)(m0 + xrow0 + it * 32) * E_ + xc4);
#pragma unroll
    for (int it = 0; it < 4; it++) {
        float4 v = xf[it];
        int row = xrow0 + it * 32;
        __half2 h01 = __floats2half2_rn(v.x, v.y);
        __half2 h23 = __floats2half2_rn(v.z, v.w);
        float2 f01 = __half22float2(h01);
        float2 f23 = __half22float2(h23);
        *reinterpret_cast<__half2*>(XhB + row * SXP + xc4)     = h01;
        *reinterpret_cast<__half2*>(XhB + row * SXP + xc4 + 2) = h23;
        *reinterpret_cast<__half2*>(XlB + row * SXP + xc4)     = __floats2half2_rn(v.x - f01.x, v.y - f01.y);
        *reinterpret_cast<__half2*>(XlB + row * SXP + xc4 + 2) = __floats2half2_rn(v.z - f23.x, v.w - f23.y);
    }
    CP_WAIT0();
    __syncthreads();

    for (int kt = 0; kt < 6; kt++) {
        const int buf  = kt & 1;
        const int nbuf = buf ^ 1;
        __half* Xh = XhB + buf * XH_SZ;
        __half* Xl = XlB + buf * XH_SZ;
        __half* Wh = WhB + buf * WH_SZ;
        __half* Wl = WlB + buf * WH_SZ;

        // ---- issue next chunk's W cp.async + X LDG (hidden under mma) ----
        if (kt < 5) {
            const int k1 = (kt + 1) * 64;
            __half* WhN = WhB + nbuf * WH_SZ;
            __half* WlN = WlB + nbuf * WH_SZ;
#pragma unroll
            for (int it = 0; it < 3; it++) {
                int r = wr + it * 64;
                cp_async16(WhN + r * SWP + wu * 8, g_Wh + (size_t)r * E_ + k1 + wu * 8);
            }
#pragma unroll
            for (int it = 0; it < 3; it++) {
                int r = wr + it * 64;
                cp_async16(WlN + r * SWP + wu * 8, g_Wl + (size_t)r * E_ + k1 + wu * 8);
            }
            CP_COMMIT();
#pragma unroll
            for (int it = 0; it < 4; it++)
                xf[it] = *reinterpret_cast<const float4*>(
                    X + (size_t)(m0 + xrow0 + it * 32) * E_ + k1 + xc4);
        }

        // ---- mma over current buffers; 3 passes for RAW distance ----
#pragma unroll
        for (int ks = 0; ks < 4; ks++) {
            const int kb = ks * 16;
            unsigned a[2][4], al[2][4], bh[3][4], bl[3][4];
#pragma unroll
            for (int mf = 0; mf < 2; mf++)
                ldm_x4(a[mf], smem_u32(Xh + (wm * 32 + mf * 16 + ar) * SXP + kb + ac));
#pragma unroll
            for (int bp = 0; bp < 3; bp++)
                ldm_x4(bh[bp], smem_u32(Wh + (wn * 48 + bp * 16 + br) * SWP + kb + bc));
            // pass 1: hi*hi
#pragma unroll
            for (int mf = 0; mf < 2; mf++)
#pragma unroll
                for (int bp = 0; bp < 3; bp++) {
                    mma16816(acc[mf][2 * bp],     a[mf], bh[bp][0], bh[bp][1]);
                    mma16816(acc[mf][2 * bp + 1], a[mf], bh[bp][2], bh[bp][3]);
                }
#pragma unroll
            for (int bp = 0; bp < 3; bp++)
                ldm_x4(bl[bp], smem_u32(Wl + (wn * 48 + bp * 16 + br) * SWP + kb + bc));
            // pass 2: hi*lo
#pragma unroll
            for (int mf = 0; mf < 2; mf++)
#pragma unroll
                for (int bp = 0; bp < 3; bp++) {
                    mma16816(acc[mf][2 * bp],     a[mf], bl[bp][0], bl[bp][1]);
                    mma16816(acc[mf][2 * bp + 1], a[mf], bl[bp][2], bl[bp][3]);
                }
#pragma unroll
            for (int mf = 0; mf < 2; mf++)
                ldm_x4(al[mf], smem_u32(Xl + (wm * 32 + mf * 16 + ar) * SXP + kb + ac));
            // pass 3: lo*hi
#pragma unroll
            for (int mf = 0; mf < 2; mf++)
#pragma unroll
                for (int bp = 0; bp < 3; bp++) {
                    mma16816(acc[mf][2 * bp],     al[mf], bh[bp][0], bh[bp][1]);
                    mma16816(acc[mf][2 * bp + 1], al[mf], bh[bp][2], bh[bp][3]);
                }
        }

        // ---- convert next X into alternate buffer (after mma issue) ----
        if (kt < 5) {
            __half* XhN = XhB + nbuf * XH_SZ;
            __half* XlN = XlB + nbuf * XH_SZ;
#pragma unroll
            for (int it = 0; it < 4; it++) {
                float4 v = xf[it];
                int row = xrow0 + it * 32;
                __half2 h01 = __floats2half2_rn(v.x, v.y);
                __half2 h23 = __floats2half2_rn(v.z, v.w);
                float2 f01 = __half22float2(h01);
                float2 f23 = __half22float2(h23);
                *reinterpret_cast<__half2*>(XhN + row * SXP + xc4)     = h01;
                *reinterpret_cast<__half2*>(XhN + row * SXP + xc4 + 2) = h23;
                *reinterpret_cast<__half2*>(XlN + row * SXP + xc4)     = __floats2half2_rn(v.x - f01.x, v.y - f01.y);
                *reinterpret_cast<__half2*>(XlN + row * SXP + xc4 + 2) = __floats2half2_rn(v.z - f23.x, v.w - f23.y);
            }
        }
        CP_WAIT0();
        __syncthreads();
    }

    // --- epilogue: write Q, K (row-major fp16) and V transposed ---
    const int g  = lane >> 2;
    const int cc = (lane & 3) << 1;
#pragma unroll
    for (int mf = 0; mf < 2; mf++) {
#pragma unroll
        for (int nf = 0; nf < 6; nf++) {
            int n   = wn * 48 + nf * 8 + cc;
            int m_a = m0 + wm * 32 + mf * 16 + g;
            int m_b = m_a + 8;
            float* c = acc[mf][nf];
            if (n < 64) {
                *reinterpret_cast<__half2*>(g_Q + (size_t)m_a * D_ + n) = __floats2half2_rn(c[0], c[1]);
                *reinterpret_cast<__half2*>(g_Q + (size_t)m_b * D_ + n) = __floats2half2_rn(c[2], c[3]);
            } else if (n < 128) {
                int nn = n - 64;
                *reinterpret_cast<__half2*>(g_K + (size_t)m_a * D_ + nn) = __floats2half2_rn(c[0], c[1]);
                *reinterpret_cast<__half2*>(g_K + (size_t)m_b * D_ + nn) = __floats2half2_rn(c[2], c[3]);
            } else {
                int nn = n - 128;
                int bidx = m_a >> 8;
                int sa = m_a & 255;
                size_t base = ((size_t)bidx * D_ + nn) * S_;
                g_Vt[base + sa]          = __float2half_rn(c[0]);
                g_Vt[base + S_ + sa]     = __float2half_rn(c[1]);
                g_Vt[base + sa + 8]      = __float2half_rn(c[2]);
                g_Vt[base + S_ + sa + 8] = __float2half_rn(c[3]);
            }
        }
    }
}

// ---------------------------------------------------------------------------
// Kernel 2: causal attention. One CTA per (batch, 128-query tile).
// 8 warps x 16 query rows; online softmax over 64-key blocks. 2 CTAs/SM.
// ---------------------------------------------------------------------------
#define SQP 72
#define SKP 72
#define SVP 264

__global__ __launch_bounds__(256, 2)
void attn_kernel(float* __restrict__ O) {
    extern __shared__ __half sm2[];
    __half* Qs = sm2;                   // [128][72]
    __half* Ks = Qs + 128 * SQP;        // [256][72]
    __half* Vs = Ks + 256 * SKP;        // [64][264] (rows = d, cols = key)

    const int tid  = threadIdx.x;
    const int lane = tid & 31;
    const int warp = tid >> 5;
    const int b    = blockIdx.y;
    const int qb   = blockIdx.x * 128;

    const __half* gq = g_Q + ((size_t)b * S_ + qb) * D_;
#pragma unroll
    for (int it = 0; it < 4; it++) {
        int idx = tid + it * 256;           // 1024 uint4
        int row = idx >> 3, c = (idx & 7) << 3;
        *reinterpret_cast<uint4*>(Qs + row * SQP + c) =
            *reinterpret_cast<const uint4*>(gq + row * D_ + c);
    }
    const __half* gk = g_K + (size_t)b * S_ * D_;
#pragma unroll
    for (int it = 0; it < 8; it++) {
        int idx = tid + it * 256;           // 2048 uint4
        int row = idx >> 3, c = (idx & 7) << 3;
        *reinterpret_cast<uint4*>(Ks + row * SKP + c) =
            *reinterpret_cast<const uint4*>(gk + row * D_ + c);
    }
    const __half* gv = g_Vt + (size_t)b * D_ * S_;
#pragma unroll
    for (int it = 0; it < 8; it++) {
        int idx = tid + it * 256;           // 2048 uint4
        int row = idx >> 5, c = (idx & 31) << 3;
        *reinterpret_cast<uint4*>(Vs + row * SVP + c) =
            *reinterpret_cast<const uint4*>(gv + row * S_ + c);
    }
    __syncthreads();

    const int ar = lane & 15;
    const int ac = (lane >> 4) << 3;
    const int br = (lane & 7) + ((lane >> 4) << 3);
    const int bc = ((lane >> 3) & 1) << 3;
    const int g  = lane >> 2;
    const int cc = (lane & 3) << 1;

    unsigned qa[4][4];
#pragma unroll
    for (int kf = 0; kf < 4; kf++)
        ldm_x4(qa[kf], smem_u32(Qs + (warp * 16 + ar) * SQP + kf * 16 + ac));

    float o[8][4];
#pragma unroll
    for (int i = 0; i < 8; i++)
#pragma unroll
        for (int j = 0; j < 4; j++) o[i][j] = 0.f;
    float mrow0 = -1e30f, mrow1 = -1e30f;
    float lrow0 = 0.f, lrow1 = 0.f;
    const int row0 = qb + warp * 16 + g;                 // thread owns row0, row0+8
    const int nkb  = ((qb + warp * 16 + 15) >> 6) + 1;   // causal early exit

    for (int kb = 0; kb < nkb; kb++) {
        float s[8][4];
#pragma unroll
        for (int i = 0; i < 8; i++)
#pragma unroll
            for (int j = 0; j < 4; j++) s[i][j] = 0.f;
        // S = Q K^T  (k over d=64)
#pragma unroll
        for (int kf = 0; kf < 4; kf++) {
#pragma unroll
            for (int bp = 0; bp < 4; bp++) {
                unsigned bk[4];
                ldm_x4(bk, smem_u32(Ks + (kb * 64 + bp * 16 + br) * SKP + kf * 16 + bc));
                mma16816(s[2 * bp],     qa[kf], bk[0], bk[1]);
                mma16816(s[2 * bp + 1], qa[kf], bk[2], bk[3]);
            }
        }
        // scale + causal mask + running max
        float mx0 = -1e30f, mx1 = -1e30f;
#pragma unroll
        for (int nf = 0; nf < 8; nf++) {
            int col = kb * 64 + nf * 8 + cc;
            s[nf][0] = (col     <= row0)     ? s[nf][0] * 0.125f : -1e30f;
            s[nf][1] = (col + 1 <= row0)     ? s[nf][1] * 0.125f : -1e30f;
            s[nf][2] = (col     <= row0 + 8) ? s[nf][2] * 0.125f : -1e30f;
            s[nf][3] = (col + 1 <= row0 + 8) ? s[nf][3] * 0.125f : -1e30f;
            mx0 = fmaxf(mx0, fmaxf(s[nf][0], s[nf][1]));
            mx1 = fmaxf(mx1, fmaxf(s[nf][2], s[nf][3]));
        }
        mx0 = fmaxf(mx0, __shfl_xor_sync(0xffffffffu, mx0, 1));
        mx0 = fmaxf(mx0, __shfl_xor_sync(0xffffffffu, mx0, 2));
        mx1 = fmaxf(mx1, __shfl_xor_sync(0xffffffffu, mx1, 1));
        mx1 = fmaxf(mx1, __shfl_xor_sync(0xffffffffu, mx1, 2));
        float mn0 = fmaxf(mrow0, mx0);
        float mn1 = fmaxf(mrow1, mx1);
        float f0 = __expf(mrow0 - mn0);
        float f1 = __expf(mrow1 - mn1);
        mrow0 = mn0; mrow1 = mn1;

        float sum0 = 0.f, sum1 = 0.f;
#pragma unroll
        for (int nf = 0; nf < 8; nf++) {
            s[nf][0] = __expf(s[nf][0] - mn0);
            s[nf][1] = __expf(s[nf][1] - mn0);
            s[nf][2] = __expf(s[nf][2] - mn1);
            s[nf][3] = __expf(s[nf][3] - mn1);
            sum0 += s[nf][0] + s[nf][1];
            sum1 += s[nf][2] + s[nf][3];
        }
        sum0 += __shfl_xor_sync(0xffffffffu, sum0, 1);
        sum0 += __shfl_xor_sync(0xffffffffu, sum0, 2);
        sum1 += __shfl_xor_sync(0xffffffffu, sum1, 1);
        sum1 += __shfl_xor_sync(0xffffffffu, sum1, 2);
        lrow0 = lrow0 * f0 + sum0;
        lrow1 = lrow1 * f1 + sum1;
#pragma unroll
        for (int nf = 0; nf < 8; nf++) {
            o[nf][0] *= f0; o[nf][1] *= f0;
            o[nf][2] *= f1; o[nf][3] *= f1;
        }
        // P (C layout) -> A fragments (register reuse, no smem round-trip)
        unsigned pa[4][4];
#pragma unroll
        for (int j = 0; j < 4; j++) {
            pa[j][0] = pack_h2(s[2 * j][0],     s[2 * j][1]);
            pa[j][1] = pack_h2(s[2 * j][2],     s[2 * j][3]);
            pa[j][2] = pack_h2(s[2 * j + 1][0], s[2 * j + 1][1]);
            pa[j][3] = pack_h2(s[2 * j + 1][2], s[2 * j + 1][3]);
        }
        // O += P @ V  (k over 64 keys of this block; B from V^T rows = d)
#pragma unroll
        for (int j = 0; j < 4; j++) {
#pragma unroll
            for (int bp = 0; bp < 4; bp++) {
                unsigned bv[4];
                ldm_x4(bv, smem_u32(Vs + (bp * 16 + br) * SVP + kb * 64 + j * 16 + bc));
                mma16816(o[2 * bp],     pa[j], bv[0], bv[1]);
                mma16816(o[2 * bp + 1], pa[j], bv[2], bv[3]);
            }
        }
    }

    const float i0 = 1.f / lrow0;
    const float i1 = 1.f / lrow1;
    float* gout = O + (size_t)b * S_ * D_;
#pragma unroll
    for (int nf = 0; nf < 8; nf++) {
        int col = nf * 8 + cc;
        float2 v0 = make_float2(o[nf][0] * i0, o[nf][1] * i0);
        float2 v1 = make_float2(o[nf][2] * i1, o[nf][3] * i1);
        *reinterpret_cast<float2*>(gout + (size_t)row0 * D_ + col)       = v0;
        *reinterpret_cast<float2*>(gout + (size_t)(row0 + 8) * D_ + col) = v1;
    }
}

// ---------------------------------------------------------------------------
extern "C" void kernel_launch(void* const* d_in, const int* in_sizes, int n_in,
                              void* d_out, int out_size) {
    (void)in_sizes; (void)n_in; (void)out_size;
    // metadata order: input_tensor, Wk, Wq, Wv
    const float* X  = (const float*)d_in[0];
    const float* Wk = (const float*)d_in[1];
    const float* Wq = (const float*)d_in[2];
    const float* Wv = (const float*)d_in[3];
    float* O = (float*)d_out;

    const int smem1 = (4 * XH_SZ + 4 * WH_SZ) * (int)sizeof(__half);           // 184320
    const int smem2 = (128 * SQP + 256 * SKP + 64 * SVP) * (int)sizeof(__half); // 89088
    cudaFuncSetAttribute(proj_kernel, cudaFuncAttributeMaxDynamicSharedMemorySize, smem1);
    cudaFuncSetAttribute(attn_kernel, cudaFuncAttributeMaxDynamicSharedMemorySize, smem2);

    wsplit_kernel<<<(E_ * D_ + 255) / 256, 256>>>(Wq, Wk, Wv);
    proj_kernel<<<1024, 512, smem1>>>(X);
    attn_kernel<<<dim3(2, B_), 256, smem2>>>(O);
}

// round 8
// speedup vs baseline: 1.3798x; 1.0008x over previous
#include <cuda_runtime.h>
#include <cuda_fp16.h>

#define B_ 512
#define S_ 256
#define E_ 384
#define D_ 64

// fp16 scratch (allocation-free __device__ globals), 16B-aligned for vector ops
__device__ __align__(16) __half g_Q[B_ * S_ * D_];          // [B*S][64]
__device__ __align__(16) __half g_K[B_ * S_ * D_];          // [B*S][64]
__device__ __align__(16) __half g_Vt[B_ * D_ * S_];         // [B][64][256]  (V transposed)
// pre-split weights, n-major: [192 rows = Q|K|V outputs][384 k]
__device__ __align__(16) __half g_Wh[192 * E_];
__device__ __align__(16) __half g_Wl[192 * E_];

__device__ __forceinline__ unsigned smem_u32(const void* p) {
    return (unsigned)__cvta_generic_to_shared(p);
}

__device__ __forceinline__ void ldm_x4(unsigned* r, unsigned addr) {
    asm volatile("ldmatrix.sync.aligned.m8n8.x4.shared.b16 {%0,%1,%2,%3}, [%4];\n"
                 : "=r"(r[0]), "=r"(r[1]), "=r"(r[2]), "=r"(r[3])
                 : "r"(addr));
}

__device__ __forceinline__ void mma16816(float* c, const unsigned* a, unsigned b0, unsigned b1) {
    asm volatile("mma.sync.aligned.m16n8k16.row.col.f32.f16.f16.f32 "
                 "{%0,%1,%2,%3}, {%4,%5,%6,%7}, {%8,%9}, {%0,%1,%2,%3};\n"
                 : "+f"(c[0]), "+f"(c[1]), "+f"(c[2]), "+f"(c[3])
                 : "r"(a[0]), "r"(a[1]), "r"(a[2]), "r"(a[3]), "r"(b0), "r"(b1));
}

__device__ __forceinline__ unsigned pack_h2(float a, float b) {
    __half2 h = __floats2half2_rn(a, b);
    return *reinterpret_cast<unsigned*>(&h);
}

__device__ __forceinline__ void cp_async16(void* dst_smem, const void* src) {
    asm volatile("cp.async.cg.shared.global [%0], [%1], 16;\n"
                 :: "r"(smem_u32(dst_smem)), "l"(src));
}
#define CP_COMMIT() asm volatile("cp.async.commit_group;\n" ::: "memory")
#define CP_WAIT0()  asm volatile("cp.async.wait_group 0;\n" ::: "memory")

// ---------------------------------------------------------------------------
// Kernel 0: split W (fp32) -> hi/lo fp16, transposed to n-major [192][384].
// ---------------------------------------------------------------------------
__global__ void wsplit_kernel(const float* __restrict__ Wq,
                              const float* __restrict__ Wk,
                              const float* __restrict__ Wv) {
    int idx = blockIdx.x * 256 + threadIdx.x;   // 0 .. E_*D_-1
    if (idx >= E_ * D_) return;
    int k = idx / D_;
    int n = idx % D_;
    float q = Wq[idx], kk = Wk[idx], v = Wv[idx];
    __half hq = __float2half_rn(q);
    g_Wh[n * E_ + k] = hq;
    g_Wl[n * E_ + k] = __float2half_rn(q - __half2float(hq));
    __half hk = __float2half_rn(kk);
    g_Wh[(64 + n) * E_ + k] = hk;
    g_Wl[(64 + n) * E_ + k] = __float2half_rn(kk - __half2float(hk));
    __half hv = __float2half_rn(v);
    g_Wh[(128 + n) * E_ + k] = hv;
    g_Wl[(128 + n) * E_ + k] = __float2half_rn(v - __half2float(hv));
}

// ---------------------------------------------------------------------------
// Kernel 1: fused Q/K/V projection, split-fp16, double-buffered cp.async.
// Per CTA: 128 rows x 192 cols (Q|K|V), K=384 in 6 chunks.
// 512 threads = 16 warps in a 4(m) x 4(n) grid; warp tile 32 x 48.
// ---------------------------------------------------------------------------
#define SXP 72   // X smem row stride (halves): 144B = 9*16 (ldmatrix-legal)
#define SWP 72   // Wt smem row stride (halves)
#define XH_SZ (128 * SXP)   // 9216 halves per X buffer
#define WH_SZ (192 * SWP)   // 13824 halves per W buffer

__global__ __launch_bounds__(512, 1)
void proj_kernel(const float* __restrict__ X) {
    extern __shared__ __half sm[];
    // layout: Xh[2] | Xl[2] | Wh[2] | Wl[2]
    __half* XhB = sm;
    __half* XlB = XhB + 2 * XH_SZ;
    __half* WhB = XlB + 2 * XH_SZ;
    __half* WlB = WhB + 2 * WH_SZ;

    const int tid  = threadIdx.x;
    const int lane = tid & 31;
    const int warp = tid >> 5;
    const int wm   = warp & 3;          // m offset: wm*32
    const int wn   = warp >> 2;         // n offset: wn*48
    const int m0   = blockIdx.x * 128;

    float acc[2][6][4];
#pragma unroll
    for (int i = 0; i < 2; i++)
#pragma unroll
        for (int j = 0; j < 6; j++)
#pragma unroll
            for (int k = 0; k < 4; k++) acc[i][j][k] = 0.f;

    const int ar = lane & 15;
    const int ac = (lane >> 4) << 3;
    const int br = (lane & 7) + ((lane >> 4) << 3);
    const int bc = ((lane >> 3) & 1) << 3;

    // X slot geometry (fixed per thread): 4 float4 per chunk
    const int xrow0 = tid >> 4;                 // rows xrow0, +32, +64, +96
    const int xc4   = (tid & 15) << 2;
    // W copy geometry: 1536 uint4 per tile half; 512 threads x 3 iters each.
    const int wr = tid >> 3;                    // base row (of 64-row groups x3)
    const int wu = tid & 7;

    // ---- prologue: W chunk 0 via cp.async, X chunk 0 via regs ----
#pragma unroll
    for (int it = 0; it < 3; it++) {
        int r = wr + it * 64;
        cp_async16(WhB + r * SWP + wu * 8, g_Wh + (size_t)r * E_ + wu * 8);
    }
#pragma unroll
    for (int it = 0; it < 3; it++) {
        int r = wr + it * 64;
        cp_async16(WlB + r * SWP + wu * 8, g_Wl + (size_t)r * E_ + wu * 8);
    }
    CP_COMMIT();

    float4 xf[4];
#pragma unroll
    for (int it = 0; it < 4; it++)
        xf[it] = *reinterpret_cast<const float4*>(X + (size_t)(m0 + xrow0 + it * 32) * E_ + xc4);
#pragma unroll
    for (int it = 0; it < 4; it++) {
        float4 v = xf[it];
        int row = xrow0 + it * 32;
        __half2 h01 = __floats2half2_rn(v.x, v.y);
        __half2 h23 = __floats2half2_rn(v.z, v.w);
        float2 f01 = __half22float2(h01);
        float2 f23 = __half22float2(h23);
        *reinterpret_cast<__half2*>(XhB + row * SXP + xc4)     = h01;
        *reinterpret_cast<__half2*>(XhB + row * SXP + xc4 + 2) = h23;
        *reinterpret_cast<__half2*>(XlB + row * SXP + xc4)     = __floats2half2_rn(v.x - f01.x, v.y - f01.y);
        *reinterpret_cast<__half2*>(XlB + row * SXP + xc4 + 2) = __floats2half2_rn(v.z - f23.x, v.w - f23.y);
    }
    CP_WAIT0();
    __syncthreads();

    for (int kt = 0; kt < 6; kt++) {
        const int buf  = kt & 1;
        const int nbuf = buf ^ 1;
        __half* Xh = XhB + buf * XH_SZ;
        __half* Xl = XlB + buf * XH_SZ;
        __half* Wh = WhB + buf * WH_SZ;
        __half* Wl = WlB + buf * WH_SZ;

        // ---- issue next chunk's W cp.async + X LDG (hidden under mma) ----
        if (kt < 5) {
            const int k1 = (kt + 1) * 64;
            __half* WhN = WhB + nbuf * WH_SZ;
            __half* WlN = WlB + nbuf * WH_SZ;
#pragma unroll
            for (int it = 0; it < 3; it++) {
                int r = wr + it * 64;
                cp_async16(WhN + r * SWP + wu * 8, g_Wh + (size_t)r * E_ + k1 + wu * 8);
            }
#pragma unroll
            for (int it = 0; it < 3; it++) {
                int r = wr + it * 64;
                cp_async16(WlN + r * SWP + wu * 8, g_Wl + (size_t)r * E_ + k1 + wu * 8);
            }
            CP_COMMIT();
#pragma unroll
            for (int it = 0; it < 4; it++)
                xf[it] = *reinterpret_cast<const float4*>(
                    X + (size_t)(m0 + xrow0 + it * 32) * E_ + k1 + xc4);
        }

        // ---- mma over current buffers; 3 passes for RAW distance ----
#pragma unroll
        for (int ks = 0; ks < 4; ks++) {
            const int kb = ks * 16;
            unsigned a[2][4], al[2][4], bh[3][4], bl[3][4];
#pragma unroll
            for (int mf = 0; mf < 2; mf++)
                ldm_x4(a[mf], smem_u32(Xh + (wm * 32 + mf * 16 + ar) * SXP + kb + ac));
#pragma unroll
            for (int bp = 0; bp < 3; bp++)
                ldm_x4(bh[bp], smem_u32(Wh + (wn * 48 + bp * 16 + br) * SWP + kb + bc));
            // pass 1: hi*hi
#pragma unroll
            for (int mf = 0; mf < 2; mf++)
#pragma unroll
                for (int bp = 0; bp < 3; bp++) {
                    mma16816(acc[mf][2 * bp],     a[mf], bh[bp][0], bh[bp][1]);
                    mma16816(acc[mf][2 * bp + 1], a[mf], bh[bp][2], bh[bp][3]);
                }
#pragma unroll
            for (int bp = 0; bp < 3; bp++)
                ldm_x4(bl[bp], smem_u32(Wl + (wn * 48 + bp * 16 + br) * SWP + kb + bc));
            // pass 2: hi*lo
#pragma unroll
            for (int mf = 0; mf < 2; mf++)
#pragma unroll
                for (int bp = 0; bp < 3; bp++) {
                    mma16816(acc[mf][2 * bp],     a[mf], bl[bp][0], bl[bp][1]);
                    mma16816(acc[mf][2 * bp + 1], a[mf], bl[bp][2], bl[bp][3]);
                }
#pragma unroll
            for (int mf = 0; mf < 2; mf++)
                ldm_x4(al[mf], smem_u32(Xl + (wm * 32 + mf * 16 + ar) * SXP + kb + ac));
            // pass 3: lo*hi
#pragma unroll
            for (int mf = 0; mf < 2; mf++)
#pragma unroll
                for (int bp = 0; bp < 3; bp++) {
                    mma16816(acc[mf][2 * bp],     al[mf], bh[bp][0], bh[bp][1]);
                    mma16816(acc[mf][2 * bp + 1], al[mf], bh[bp][2], bh[bp][3]);
                }
        }

        // ---- convert next X into alternate buffer (after mma issue) ----
        if (kt < 5) {
            __half* XhN = XhB + nbuf * XH_SZ;
            __half* XlN = XlB + nbuf * XH_SZ;
#pragma unroll
            for (int it = 0; it < 4; it++) {
                float4 v = xf[it];
                int row = xrow0 + it * 32;
                __half2 h01 = __floats2half2_rn(v.x, v.y);
                __half2 h23 = __floats2half2_rn(v.z, v.w);
                float2 f01 = __half22float2(h01);
                float2 f23 = __half22float2(h23);
                *reinterpret_cast<__half2*>(XhN + row * SXP + xc4)     = h01;
                *reinterpret_cast<__half2*>(XhN + row * SXP + xc4 + 2) = h23;
                *reinterpret_cast<__half2*>(XlN + row * SXP + xc4)     = __floats2half2_rn(v.x - f01.x, v.y - f01.y);
                *reinterpret_cast<__half2*>(XlN + row * SXP + xc4 + 2) = __floats2half2_rn(v.z - f23.x, v.w - f23.y);
            }
        }
        CP_WAIT0();
        __syncthreads();
    }

    // --- epilogue: write Q, K (row-major fp16) and V transposed ---
    const int g  = lane >> 2;
    const int cc = (lane & 3) << 1;
#pragma unroll
    for (int mf = 0; mf < 2; mf++) {
#pragma unroll
        for (int nf = 0; nf < 6; nf++) {
            int n   = wn * 48 + nf * 8 + cc;
            int m_a = m0 + wm * 32 + mf * 16 + g;
            int m_b = m_a + 8;
            float* c = acc[mf][nf];
            if (n < 64) {
                *reinterpret_cast<__half2*>(g_Q + (size_t)m_a * D_ + n) = __floats2half2_rn(c[0], c[1]);
                *reinterpret_cast<__half2*>(g_Q + (size_t)m_b * D_ + n) = __floats2half2_rn(c[2], c[3]);
            } else if (n < 128) {
                int nn = n - 64;
                *reinterpret_cast<__half2*>(g_K + (size_t)m_a * D_ + nn) = __floats2half2_rn(c[0], c[1]);
                *reinterpret_cast<__half2*>(g_K + (size_t)m_b * D_ + nn) = __floats2half2_rn(c[2], c[3]);
            } else {
                int nn = n - 128;
                int bidx = m_a >> 8;
                int sa = m_a & 255;
                size_t base = ((size_t)bidx * D_ + nn) * S_;
                g_Vt[base + sa]          = __float2half_rn(c[0]);
                g_Vt[base + S_ + sa]     = __float2half_rn(c[1]);
                g_Vt[base + sa + 8]      = __float2half_rn(c[2]);
                g_Vt[base + S_ + sa + 8] = __float2half_rn(c[3]);
            }
        }
    }
}

// ---------------------------------------------------------------------------
// Kernel 2: causal attention. One CTA per (batch, 128-query tile).
// 8 warps x 16 query rows; online softmax over 64-key blocks. 2 CTAs/SM.
// ---------------------------------------------------------------------------
#define SQP 72
#define SKP 72
#define SVP 264

__global__ __launch_bounds__(256, 2)
void attn_kernel(float* __restrict__ O) {
    extern __shared__ __half sm2[];
    __half* Qs = sm2;                   // [128][72]
    __half* Ks = Qs + 128 * SQP;        // [256][72]
    __half* Vs = Ks + 256 * SKP;        // [64][264] (rows = d, cols = key)

    const int tid  = threadIdx.x;
    const int lane = tid & 31;
    const int warp = tid >> 5;
    const int b    = blockIdx.y;
    const int qb   = blockIdx.x * 128;

    const __half* gq = g_Q + ((size_t)b * S_ + qb) * D_;
#pragma unroll
    for (int it = 0; it < 4; it++) {
        int idx = tid + it * 256;           // 1024 uint4
        int row = idx >> 3, c = (idx & 7) << 3;
        *reinterpret_cast<uint4*>(Qs + row * SQP + c) =
            *reinterpret_cast<const uint4*>(gq + row * D_ + c);
    }
    const __half* gk = g_K + (size_t)b * S_ * D_;
#pragma unroll
    for (int it = 0; it < 8; it++) {
        int idx = tid + it * 256;           // 2048 uint4
        int row = idx >> 3, c = (idx & 7) << 3;
        *reinterpret_cast<uint4*>(Ks + row * SKP + c) =
            *reinterpret_cast<const uint4*>(gk + row * D_ + c);
    }
    const __half* gv = g_Vt + (size_t)b * D_ * S_;
#pragma unroll
    for (int it = 0; it < 8; it++) {
        int idx = tid + it * 256;           // 2048 uint4
        int row = idx >> 5, c = (idx & 31) << 3;
        *reinterpret_cast<uint4*>(Vs + row * SVP + c) =
            *reinterpret_cast<const uint4*>(gv + row * S_ + c);
    }
    __syncthreads();

    const int ar = lane & 15;
    const int ac = (lane >> 4) << 3;
    const int br = (lane & 7) + ((lane >> 4) << 3);
    const int bc = ((lane >> 3) & 1) << 3;
    const int g  = lane >> 2;
    const int cc = (lane & 3) << 1;

    unsigned qa[4][4];
#pragma unroll
    for (int kf = 0; kf < 4; kf++)
        ldm_x4(qa[kf], smem_u32(Qs + (warp * 16 + ar) * SQP + kf * 16 + ac));

    float o[8][4];
#pragma unroll
    for (int i = 0; i < 8; i++)
#pragma unroll
        for (int j = 0; j < 4; j++) o[i][j] = 0.f;
    float mrow0 = -1e30f, mrow1 = -1e30f;
    float lrow0 = 0.f, lrow1 = 0.f;
    const int row0 = qb + warp * 16 + g;                 // thread owns row0, row0+8
    const int nkb  = ((qb + warp * 16 + 15) >> 6) + 1;   // causal early exit

    for (int kb = 0; kb < nkb; kb++) {
        float s[8][4];
#pragma unroll
        for (int i = 0; i < 8; i++)
#pragma unroll
            for (int j = 0; j < 4; j++) s[i][j] = 0.f;
        // S = Q K^T  (k over d=64)
#pragma unroll
        for (int kf = 0; kf < 4; kf++) {
#pragma unroll
            for (int bp = 0; bp < 4; bp++) {
                unsigned bk[4];
                ldm_x4(bk, smem_u32(Ks + (kb * 64 + bp * 16 + br) * SKP + kf * 16 + bc));
                mma16816(s[2 * bp],     qa[kf], bk[0], bk[1]);
                mma16816(s[2 * bp + 1], qa[kf], bk[2], bk[3]);
            }
        }
        // scale + causal mask + running max
        float mx0 = -1e30f, mx1 = -1e30f;
#pragma unroll
        for (int nf = 0; nf < 8; nf++) {
            int col = kb * 64 + nf * 8 + cc;
            s[nf][0] = (col     <= row0)     ? s[nf][0] * 0.125f : -1e30f;
            s[nf][1] = (col + 1 <= row0)     ? s[nf][1] * 0.125f : -1e30f;
            s[nf][2] = (col     <= row0 + 8) ? s[nf][2] * 0.125f : -1e30f;
            s[nf][3] = (col + 1 <= row0 + 8) ? s[nf][3] * 0.125f : -1e30f;
            mx0 = fmaxf(mx0, fmaxf(s[nf][0], s[nf][1]));
            mx1 = fmaxf(mx1, fmaxf(s[nf][2], s[nf][3]));
        }
        mx0 = fmaxf(mx0, __shfl_xor_sync(0xffffffffu, mx0, 1));
        mx0 = fmaxf(mx0, __shfl_xor_sync(0xffffffffu, mx0, 2));
        mx1 = fmaxf(mx1, __shfl_xor_sync(0xffffffffu, mx1, 1));
        mx1 = fmaxf(mx1, __shfl_xor_sync(0xffffffffu, mx1, 2));
        float mn0 = fmaxf(mrow0, mx0);
        float mn1 = fmaxf(mrow1, mx1);
        float f0 = __expf(mrow0 - mn0);
        float f1 = __expf(mrow1 - mn1);
        mrow0 = mn0; mrow1 = mn1;

        float sum0 = 0.f, sum1 = 0.f;
#pragma unroll
        for (int nf = 0; nf < 8; nf++) {
            s[nf][0] = __expf(s[nf][0] - mn0);
            s[nf][1] = __expf(s[nf][1] - mn0);
            s[nf][2] = __expf(s[nf][2] - mn1);
            s[nf][3] = __expf(s[nf][3] - mn1);
            sum0 += s[nf][0] + s[nf][1];
            sum1 += s[nf][2] + s[nf][3];
        }
        sum0 += __shfl_xor_sync(0xffffffffu, sum0, 1);
        sum0 += __shfl_xor_sync(0xffffffffu, sum0, 2);
        sum1 += __shfl_xor_sync(0xffffffffu, sum1, 1);
        sum1 += __shfl_xor_sync(0xffffffffu, sum1, 2);
        lrow0 = lrow0 * f0 + sum0;
        lrow1 = lrow1 * f1 + sum1;
#pragma unroll
        for (int nf = 0; nf < 8; nf++) {
            o[nf][0] *= f0; o[nf][1] *= f0;
            o[nf][2] *= f1; o[nf][3] *= f1;
        }
        // P (C layout) -> A fragments (register reuse, no smem round-trip)
        unsigned pa[4][4];
#pragma unroll
        for (int j = 0; j < 4; j++) {
            pa[j][0] = pack_h2(s[2 * j][0],     s[2 * j][1]);
            pa[j][1] = pack_h2(s[2 * j][2],     s[2 * j][3]);
            pa[j][2] = pack_h2(s[2 * j + 1][0], s[2 * j + 1][1]);
            pa[j][3] = pack_h2(s[2 * j + 1][2], s[2 * j + 1][3]);
        }
        // O += P @ V  (k over 64 keys of this block; B from V^T rows = d)
#pragma unroll
        for (int j = 0; j < 4; j++) {
#pragma unroll
            for (int bp = 0; bp < 4; bp++) {
                unsigned bv[4];
                ldm_x4(bv, smem_u32(Vs + (bp * 16 + br) * SVP + kb * 64 + j * 16 + bc));
                mma16816(o[2 * bp],     pa[j], bv[0], bv[1]);
                mma16816(o[2 * bp + 1], pa[j], bv[2], bv[3]);
            }
        }
    }

    const float i0 = 1.f / lrow0;
    const float i1 = 1.f / lrow1;
    float* gout = O + (size_t)b * S_ * D_;
#pragma unroll
    for (int nf = 0; nf < 8; nf++) {
        int col = nf * 8 + cc;
        float2 v0 = make_float2(o[nf][0] * i0, o[nf][1] * i0);
        float2 v1 = make_float2(o[nf][2] * i1, o[nf][3] * i1);
        *reinterpret_cast<float2*>(gout + (size_t)row0 * D_ + col)       = v0;
        *reinterpret_cast<float2*>(gout + (size_t)(row0 + 8) * D_ + col) = v1;
    }
}

// ---------------------------------------------------------------------------
extern "C" void kernel_launch(void* const* d_in, const int* in_sizes, int n_in,
                              void* d_out, int out_size) {
    (void)in_sizes; (void)n_in; (void)out_size;
    // metadata order: input_tensor, Wk, Wq, Wv
    const float* X  = (const float*)d_in[0];
    const float* Wk = (const float*)d_in[1];
    const float* Wq = (const float*)d_in[2];
    const float* Wv = (const float*)d_in[3];
    float* O = (float*)d_out;

    const int smem1 = (4 * XH_SZ + 4 * WH_SZ) * (int)sizeof(__half);           // 184320
    const int smem2 = (128 * SQP + 256 * SKP + 64 * SVP) * (int)sizeof(__half); // 89088
    cudaFuncSetAttribute(proj_kernel, cudaFuncAttributeMaxDynamicSharedMemorySize, smem1);
    cudaFuncSetAttribute(attn_kernel, cudaFuncAttributeMaxDynamicSharedMemorySize, smem2);

    wsplit_kernel<<<(E_ * D_ + 255) / 256, 256>>>(Wq, Wk, Wv);
    proj_kernel<<<1024, 512, smem1>>>(X);
    attn_kernel<<<dim3(2, B_), 256, smem2>>>(O);
}

// round 9
// speedup vs baseline: 1.3862x; 1.0047x over previous
#include <cuda_runtime.h>
#include <cuda_fp16.h>

#define B_ 512
#define S_ 256
#define E_ 384
#define D_ 64

// fp16 scratch (allocation-free __device__ globals), 16B-aligned for vector ops
__device__ __align__(16) __half g_Q[B_ * S_ * D_];          // [B*S][64]
__device__ __align__(16) __half g_K[B_ * S_ * D_];          // [B*S][64]
__device__ __align__(16) __half g_Vt[B_ * D_ * S_];         // [B][64][256]  (V transposed)
// pre-split weights, n-major: [192 rows = Q|K|V outputs][384 k]
__device__ __align__(16) __half g_Wh[192 * E_];
__device__ __align__(16) __half g_Wl[192 * E_];

__device__ __forceinline__ unsigned smem_u32(const void* p) {
    return (unsigned)__cvta_generic_to_shared(p);
}

__device__ __forceinline__ void ldm_x4(unsigned* r, unsigned addr) {
    asm volatile("ldmatrix.sync.aligned.m8n8.x4.shared.b16 {%0,%1,%2,%3}, [%4];\n"
                 : "=r"(r[0]), "=r"(r[1]), "=r"(r[2]), "=r"(r[3])
                 : "r"(addr));
}

__device__ __forceinline__ void mma16816(float* c, const unsigned* a, unsigned b0, unsigned b1) {
    asm volatile("mma.sync.aligned.m16n8k16.row.col.f32.f16.f16.f32 "
                 "{%0,%1,%2,%3}, {%4,%5,%6,%7}, {%8,%9}, {%0,%1,%2,%3};\n"
                 : "+f"(c[0]), "+f"(c[1]), "+f"(c[2]), "+f"(c[3])
                 : "r"(a[0]), "r"(a[1]), "r"(a[2]), "r"(a[3]), "r"(b0), "r"(b1));
}

__device__ __forceinline__ unsigned pack_h2(float a, float b) {
    __half2 h = __floats2half2_rn(a, b);
    return *reinterpret_cast<unsigned*>(&h);
}

__device__ __forceinline__ void cp_async16(void* dst_smem, const void* src) {
    asm volatile("cp.async.cg.shared.global [%0], [%1], 16;\n"
                 :: "r"(smem_u32(dst_smem)), "l"(src));
}
#define CP_COMMIT() asm volatile("cp.async.commit_group;\n" ::: "memory")
#define CP_WAIT0()  asm volatile("cp.async.wait_group 0;\n" ::: "memory")

// ---------------------------------------------------------------------------
// Kernel 0: split W (fp32) -> hi/lo fp16, transposed to n-major [192][384].
// ---------------------------------------------------------------------------
__global__ void wsplit_kernel(const float* __restrict__ Wq,
                              const float* __restrict__ Wk,
                              const float* __restrict__ Wv) {
    int idx = blockIdx.x * 256 + threadIdx.x;   // 0 .. E_*D_-1
    if (idx >= E_ * D_) return;
    int k = idx / D_;
    int n = idx % D_;
    float q = Wq[idx], kk = Wk[idx], v = Wv[idx];
    __half hq = __float2half_rn(q);
    g_Wh[n * E_ + k] = hq;
    g_Wl[n * E_ + k] = __float2half_rn(q - __half2float(hq));
    __half hk = __float2half_rn(kk);
    g_Wh[(64 + n) * E_ + k] = hk;
    g_Wl[(64 + n) * E_ + k] = __float2half_rn(kk - __half2float(hk));
    __half hv = __float2half_rn(v);
    g_Wh[(128 + n) * E_ + k] = hv;
    g_Wl[(128 + n) * E_ + k] = __float2half_rn(v - __half2float(hv));
}

// ---------------------------------------------------------------------------
// Kernel 1: fused Q/K/V projection, split-fp16, double-buffered cp.async.
// Per CTA: 128 rows x 192 cols (Q|K|V), K=384 in 6 chunks.
// 512 threads = 16 warps in a 4(m) x 4(n) grid; warp tile 32 x 48.
// ---------------------------------------------------------------------------
#define SXP 72   // X smem row stride (halves): 144B = 9*16 (ldmatrix-legal)
#define SWP 72   // Wt smem row stride (halves)
#define XH_SZ (128 * SXP)   // 9216 halves per X buffer
#define WH_SZ (192 * SWP)   // 13824 halves per W buffer

__global__ __launch_bounds__(512, 1)
void proj_kernel(const float* __restrict__ X) {
    extern __shared__ __half sm[];
    // layout: Xh[2] | Xl[2] | Wh[2] | Wl[2]
    __half* XhB = sm;
    __half* XlB = XhB + 2 * XH_SZ;
    __half* WhB = XlB + 2 * XH_SZ;
    __half* WlB = WhB + 2 * WH_SZ;

    const int tid  = threadIdx.x;
    const int lane = tid & 31;
    const int warp = tid >> 5;
    const int wm   = warp & 3;          // m offset: wm*32
    const int wn   = warp >> 2;         // n offset: wn*48
    const int m0   = blockIdx.x * 128;

    float acc[2][6][4];
#pragma unroll
    for (int i = 0; i < 2; i++)
#pragma unroll
        for (int j = 0; j < 6; j++)
#pragma unroll
            for (int k = 0; k < 4; k++) acc[i][j][k] = 0.f;

    const int ar = lane & 15;
    const int ac = (lane >> 4) << 3;
    const int br = (lane & 7) + ((lane >> 4) << 3);
    const int bc = ((lane >> 3) & 1) << 3;

    // X slot geometry (fixed per thread): 4 float4 per chunk
    const int xrow0 = tid >> 4;                 // rows xrow0, +32, +64, +96
    const int xc4   = (tid & 15) << 2;
    // W copy geometry: 1536 uint4 per tile half; 512 threads x 3 iters each.
    const int wr = tid >> 3;                    // base row (of 64-row groups x3)
    const int wu = tid & 7;

    // ---- prologue: W chunk 0 via cp.async, X chunk 0 via regs ----
#pragma unroll
    for (int it = 0; it < 3; it++) {
        int r = wr + it * 64;
        cp_async16(WhB + r * SWP + wu * 8, g_Wh + (size_t)r * E_ + wu * 8);
    }
#pragma unroll
    for (int it = 0; it < 3; it++) {
        int r = wr + it * 64;
        cp_async16(WlB + r * SWP + wu * 8, g_Wl + (size_t)r * E_ + wu * 8);
    }
    CP_COMMIT();

    float4 xf[4];
#pragma unroll
    for (int it = 0; it < 4; it++)
        xf[it] = *reinterpret_cast<const float4*>(X + (size_t)(m0 + xrow0 + it * 32) * E_ + xc4);
#pragma unroll
    for (int it = 0; it < 4; it++) {
        float4 v = xf[it];
        int row = xrow0 + it * 32;
        __half2 h01 = __floats2half2_rn(v.x, v.y);
        __half2 h23 = __floats2half2_rn(v.z, v.w);
        float2 f01 = __half22float2(h01);
        float2 f23 = __half22float2(h23);
        *reinterpret_cast<__half2*>(XhB + row * SXP + xc4)     = h01;
        *reinterpret_cast<__half2*>(XhB + row * SXP + xc4 + 2) = h23;
        *reinterpret_cast<__half2*>(XlB + row * SXP + xc4)     = __floats2half2_rn(v.x - f01.x, v.y - f01.y);
        *reinterpret_cast<__half2*>(XlB + row * SXP + xc4 + 2) = __floats2half2_rn(v.z - f23.x, v.w - f23.y);
    }
    CP_WAIT0();
    __syncthreads();

    for (int kt = 0; kt < 6; kt++) {
        const int buf  = kt & 1;
        const int nbuf = buf ^ 1;
        __half* Xh = XhB + buf * XH_SZ;
        __half* Xl = XlB + buf * XH_SZ;
        __half* Wh = WhB + buf * WH_SZ;
        __half* Wl = WlB + buf * WH_SZ;

        // ---- issue next chunk's W cp.async + X LDG (hidden under mma) ----
        if (kt < 5) {
            const int k1 = (kt + 1) * 64;
            __half* WhN = WhB + nbuf * WH_SZ;
            __half* WlN = WlB + nbuf * WH_SZ;
#pragma unroll
            for (int it = 0; it < 3; it++) {
                int r = wr + it * 64;
                cp_async16(WhN + r * SWP + wu * 8, g_Wh + (size_t)r * E_ + k1 + wu * 8);
            }
#pragma unroll
            for (int it = 0; it < 3; it++) {
                int r = wr + it * 64;
                cp_async16(WlN + r * SWP + wu * 8, g_Wl + (size_t)r * E_ + k1 + wu * 8);
            }
            CP_COMMIT();
#pragma unroll
            for (int it = 0; it < 4; it++)
                xf[it] = *reinterpret_cast<const float4*>(
                    X + (size_t)(m0 + xrow0 + it * 32) * E_ + k1 + xc4);
        }

        // ---- mma over current buffers; 3 passes for RAW distance ----
#pragma unroll
        for (int ks = 0; ks < 4; ks++) {
            const int kb = ks * 16;
            unsigned a[2][4], al[2][4], bh[3][4], bl[3][4];
#pragma unroll
            for (int mf = 0; mf < 2; mf++)
                ldm_x4(a[mf], smem_u32(Xh + (wm * 32 + mf * 16 + ar) * SXP + kb + ac));
#pragma unroll
            for (int bp = 0; bp < 3; bp++)
                ldm_x4(bh[bp], smem_u32(Wh + (wn * 48 + bp * 16 + br) * SWP + kb + bc));
            // pass 1: hi*hi
#pragma unroll
            for (int mf = 0; mf < 2; mf++)
#pragma unroll
                for (int bp = 0; bp < 3; bp++) {
                    mma16816(acc[mf][2 * bp],     a[mf], bh[bp][0], bh[bp][1]);
                    mma16816(acc[mf][2 * bp + 1], a[mf], bh[bp][2], bh[bp][3]);
                }
#pragma unroll
            for (int bp = 0; bp < 3; bp++)
                ldm_x4(bl[bp], smem_u32(Wl + (wn * 48 + bp * 16 + br) * SWP + kb + bc));
            // pass 2: hi*lo
#pragma unroll
            for (int mf = 0; mf < 2; mf++)
#pragma unroll
                for (int bp = 0; bp < 3; bp++) {
                    mma16816(acc[mf][2 * bp],     a[mf], bl[bp][0], bl[bp][1]);
                    mma16816(acc[mf][2 * bp + 1], a[mf], bl[bp][2], bl[bp][3]);
                }
#pragma unroll
            for (int mf = 0; mf < 2; mf++)
                ldm_x4(al[mf], smem_u32(Xl + (wm * 32 + mf * 16 + ar) * SXP + kb + ac));
            // pass 3: lo*hi
#pragma unroll
            for (int mf = 0; mf < 2; mf++)
#pragma unroll
                for (int bp = 0; bp < 3; bp++) {
                    mma16816(acc[mf][2 * bp],     al[mf], bh[bp][0], bh[bp][1]);
                    mma16816(acc[mf][2 * bp + 1], al[mf], bh[bp][2], bh[bp][3]);
                }
        }

        // ---- convert next X into alternate buffer (after mma issue) ----
        if (kt < 5) {
            __half* XhN = XhB + nbuf * XH_SZ;
            __half* XlN = XlB + nbuf * XH_SZ;
#pragma unroll
            for (int it = 0; it < 4; it++) {
                float4 v = xf[it];
                int row = xrow0 + it * 32;
                __half2 h01 = __floats2half2_rn(v.x, v.y);
                __half2 h23 = __floats2half2_rn(v.z, v.w);
                float2 f01 = __half22float2(h01);
                float2 f23 = __half22float2(h23);
                *reinterpret_cast<__half2*>(XhN + row * SXP + xc4)     = h01;
                *reinterpret_cast<__half2*>(XhN + row * SXP + xc4 + 2) = h23;
                *reinterpret_cast<__half2*>(XlN + row * SXP + xc4)     = __floats2half2_rn(v.x - f01.x, v.y - f01.y);
                *reinterpret_cast<__half2*>(XlN + row * SXP + xc4 + 2) = __floats2half2_rn(v.z - f23.x, v.w - f23.y);
            }
        }
        CP_WAIT0();
        __syncthreads();
    }

    // --- epilogue: write Q, K (row-major fp16) and V transposed ---
    const int g  = lane >> 2;
    const int cc = (lane & 3) << 1;
#pragma unroll
    for (int mf = 0; mf < 2; mf++) {
#pragma unroll
        for (int nf = 0; nf < 6; nf++) {
            int n   = wn * 48 + nf * 8 + cc;
            int m_a = m0 + wm * 32 + mf * 16 + g;
            int m_b = m_a + 8;
            float* c = acc[mf][nf];
            if (n < 64) {
                *reinterpret_cast<__half2*>(g_Q + (size_t)m_a * D_ + n) = __floats2half2_rn(c[0], c[1]);
                *reinterpret_cast<__half2*>(g_Q + (size_t)m_b * D_ + n) = __floats2half2_rn(c[2], c[3]);
            } else if (n < 128) {
                int nn = n - 64;
                *reinterpret_cast<__half2*>(g_K + (size_t)m_a * D_ + nn) = __floats2half2_rn(c[0], c[1]);
                *reinterpret_cast<__half2*>(g_K + (size_t)m_b * D_ + nn) = __floats2half2_rn(c[2], c[3]);
            } else {
                int nn = n - 128;
                int bidx = m_a >> 8;
                int sa = m_a & 255;
                size_t base = ((size_t)bidx * D_ + nn) * S_;
                g_Vt[base + sa]          = __float2half_rn(c[0]);
                g_Vt[base + S_ + sa]     = __float2half_rn(c[1]);
                g_Vt[base + sa + 8]      = __float2half_rn(c[2]);
                g_Vt[base + S_ + sa + 8] = __float2half_rn(c[3]);
            }
        }
    }
}

// ---------------------------------------------------------------------------
// Kernel 2: causal attention. One CTA per (batch, 128-query tile).
// 8 warps x 16 query rows; online softmax over 64-key blocks. 2 CTAs/SM.
// ---------------------------------------------------------------------------
#define SQP 72
#define SKP 72
#define SVP 264

__global__ __launch_bounds__(256, 2)
void attn_kernel(float* __restrict__ O) {
    extern __shared__ __half sm2[];
    __half* Qs = sm2;                   // [128][72]
    __half* Ks = Qs + 128 * SQP;        // [256][72]
    __half* Vs = Ks + 256 * SKP;        // [64][264] (rows = d, cols = key)

    const int tid  = threadIdx.x;
    const int lane = tid & 31;
    const int warp = tid >> 5;
    const int b    = blockIdx.y;
    const int qb   = blockIdx.x * 128;

    const __half* gq = g_Q + ((size_t)b * S_ + qb) * D_;
#pragma unroll
    for (int it = 0; it < 4; it++) {
        int idx = tid + it * 256;           // 1024 uint4
        int row = idx >> 3, c = (idx & 7) << 3;
        *reinterpret_cast<uint4*>(Qs + row * SQP + c) =
            *reinterpret_cast<const uint4*>(gq + row * D_ + c);
    }
    const __half* gk = g_K + (size_t)b * S_ * D_;
#pragma unroll
    for (int it = 0; it < 8; it++) {
        int idx = tid + it * 256;           // 2048 uint4
        int row = idx >> 3, c = (idx & 7) << 3;
        *reinterpret_cast<uint4*>(Ks + row * SKP + c) =
            *reinterpret_cast<const uint4*>(gk + row * D_ + c);
    }
    const __half* gv = g_Vt + (size_t)b * D_ * S_;
#pragma unroll
    for (int it = 0; it < 8; it++) {
        int idx = tid + it * 256;           // 2048 uint4
        int row = idx >> 5, c = (idx & 31) << 3;
        *reinterpret_cast<uint4*>(Vs + row * SVP + c) =
            *reinterpret_cast<const uint4*>(gv + row * S_ + c);
    }
    __syncthreads();

    const int ar = lane & 15;
    const int ac = (lane >> 4) << 3;
    const int br = (lane & 7) + ((lane >> 4) << 3);
    const int bc = ((lane >> 3) & 1) << 3;
    const int g  = lane >> 2;
    const int cc = (lane & 3) << 1;

    unsigned qa[4][4];
#pragma unroll
    for (int kf = 0; kf < 4; kf++)
        ldm_x4(qa[kf], smem_u32(Qs + (warp * 16 + ar) * SQP + kf * 16 + ac));

    float o[8][4];
#pragma unroll
    for (int i = 0; i < 8; i++)
#pragma unroll
        for (int j = 0; j < 4; j++) o[i][j] = 0.f;
    float mrow0 = -1e30f, mrow1 = -1e30f;
    float lrow0 = 0.f, lrow1 = 0.f;
    const int row0 = qb + warp * 16 + g;                 // thread owns row0, row0+8
    const int nkb  = ((qb + warp * 16 + 15) >> 6) + 1;   // causal early exit

    for (int kb = 0; kb < nkb; kb++) {
        float s[8][4];
#pragma unroll
        for (int i = 0; i < 8; i++)
#pragma unroll
            for (int j = 0; j < 4; j++) s[i][j] = 0.f;
        // S = Q K^T  (k over d=64)
#pragma unroll
        for (int kf = 0; kf < 4; kf++) {
#pragma unroll
            for (int bp = 0; bp < 4; bp++) {
                unsigned bk[4];
                ldm_x4(bk, smem_u32(Ks + (kb * 64 + bp * 16 + br) * SKP + kf * 16 + bc));
                mma16816(s[2 * bp],     qa[kf], bk[0], bk[1]);
                mma16816(s[2 * bp + 1], qa[kf], bk[2], bk[3]);
            }
        }
        // scale + causal mask + running max
        float mx0 = -1e30f, mx1 = -1e30f;
#pragma unroll
        for (int nf = 0; nf < 8; nf++) {
            int col = kb * 64 + nf * 8 + cc;
            s[nf][0] = (col     <= row0)     ? s[nf][0] * 0.125f : -1e30f;
            s[nf][1] = (col + 1 <= row0)     ? s[nf][1] * 0.125f : -1e30f;
            s[nf][2] = (col     <= row0 + 8) ? s[nf][2] * 0.125f : -1e30f;
            s[nf][3] = (col + 1 <= row0 + 8) ? s[nf][3] * 0.125f : -1e30f;
            mx0 = fmaxf(mx0, fmaxf(s[nf][0], s[nf][1]));
            mx1 = fmaxf(mx1, fmaxf(s[nf][2], s[nf][3]));
        }
        mx0 = fmaxf(mx0, __shfl_xor_sync(0xffffffffu, mx0, 1));
        mx0 = fmaxf(mx0, __shfl_xor_sync(0xffffffffu, mx0, 2));
        mx1 = fmaxf(mx1, __shfl_xor_sync(0xffffffffu, mx1, 1));
        mx1 = fmaxf(mx1, __shfl_xor_sync(0xffffffffu, mx1, 2));
        float mn0 = fmaxf(mrow0, mx0);
        float mn1 = fmaxf(mrow1, mx1);
        float f0 = __expf(mrow0 - mn0);
        float f1 = __expf(mrow1 - mn1);
        mrow0 = mn0; mrow1 = mn1;

        float sum0 = 0.f, sum1 = 0.f;
#pragma unroll
        for (int nf = 0; nf < 8; nf++) {
            s[nf][0] = __expf(s[nf][0] - mn0);
            s[nf][1] = __expf(s[nf][1] - mn0);
            s[nf][2] = __expf(s[nf][2] - mn1);
            s[nf][3] = __expf(s[nf][3] - mn1);
            sum0 += s[nf][0] + s[nf][1];
            sum1 += s[nf][2] + s[nf][3];
        }
        sum0 += __shfl_xor_sync(0xffffffffu, sum0, 1);
        sum0 += __shfl_xor_sync(0xffffffffu, sum0, 2);
        sum1 += __shfl_xor_sync(0xffffffffu, sum1, 1);
        sum1 += __shfl_xor_sync(0xffffffffu, sum1, 2);
        lrow0 = lrow0 * f0 + sum0;
        lrow1 = lrow1 * f1 + sum1;
#pragma unroll
        for (int nf = 0; nf < 8; nf++) {
            o[nf][0] *= f0; o[nf][1] *= f0;
            o[nf][2] *= f1; o[nf][3] *= f1;
        }
        // P (C layout) -> A fragments (register reuse, no smem round-trip)
        unsigned pa[4][4];
#pragma unroll
        for (int j = 0; j < 4; j++) {
            pa[j][0] = pack_h2(s[2 * j][0],     s[2 * j][1]);
            pa[j][1] = pack_h2(s[2 * j][2],     s[2 * j][3]);
            pa[j][2] = pack_h2(s[2 * j + 1][0], s[2 * j + 1][1]);
            pa[j][3] = pack_h2(s[2 * j + 1][2], s[2 * j + 1][3]);
        }
        // O += P @ V  (k over 64 keys of this block; B from V^T rows = d)
#pragma unroll
        for (int j = 0; j < 4; j++) {
#pragma unroll
            for (int bp = 0; bp < 4; bp++) {
                unsigned bv[4];
                ldm_x4(bv, smem_u32(Vs + (bp * 16 + br) * SVP + kb * 64 + j * 16 + bc));
                mma16816(o[2 * bp],     pa[j], bv[0], bv[1]);
                mma16816(o[2 * bp + 1], pa[j], bv[2], bv[3]);
            }
        }
    }

    const float i0 = 1.f / lrow0;
    const float i1 = 1.f / lrow1;
    float* gout = O + (size_t)b * S_ * D_;
#pragma unroll
    for (int nf = 0; nf < 8; nf++) {
        int col = nf * 8 + cc;
        float2 v0 = make_float2(o[nf][0] * i0, o[nf][1] * i0);
        float2 v1 = make_float2(o[nf][2] * i1, o[nf][3] * i1);
        *reinterpret_cast<float2*>(gout + (size_t)row0 * D_ + col)       = v0;
        *reinterpret_cast<float2*>(gout + (size_t)(row0 + 8) * D_ + col) = v1;
    }
}

// ---------------------------------------------------------------------------
extern "C" void kernel_launch(void* const* d_in, const int* in_sizes, int n_in,
                              void* d_out, int out_size) {
    (void)in_sizes; (void)n_in; (void)out_size;
    // metadata order: input_tensor, Wk, Wq, Wv
    const float* X  = (const float*)d_in[0];
    const float* Wk = (const float*)d_in[1];
    const float* Wq = (const float*)d_in[2];
    const float* Wv = (const float*)d_in[3];
    float* O = (float*)d_out;

    const int smem1 = (4 * XH_SZ + 4 * WH_SZ) * (int)sizeof(__half);           // 184320
    const int smem2 = (128 * SQP + 256 * SKP + 64 * SVP) * (int)sizeof(__half); // 89088
    cudaFuncSetAttribute(proj_kernel, cudaFuncAttributeMaxDynamicSharedMemorySize, smem1);
    cudaFuncSetAttribute(attn_kernel, cudaFuncAttributeMaxDynamicSharedMemorySize, smem2);

    wsplit_kernel<<<(E_ * D_ + 255) / 256, 256>>>(Wq, Wk, Wv);
    proj_kernel<<<1024, 512, smem1>>>(X);
    attn_kernel<<<dim3(2, B_), 256, smem2>>>(O);
}